// round 13
// baseline (speedup 1.0000x reference)
#include <cuda_runtime.h>

#define TPC 129                                     // compact tile pitch (h dim)
#define SPITCH 136                                  // padded staging row pitch (128 + 8)
#define NF_MAX 2850
#define CTILE_CPLX (64 * TPC)                       // 8256 cplx
#define STG_CPLX   (12 * 2 * SPITCH)                // 3264 cplx
#define SMEM_BYTES ((CTILE_CPLX + STG_CPLX) * 8)    // 92160 B

// ---------------- device scratch ------------------------------------------------
__device__ float2 g_E[128];
__device__ int    g_maskUV[NF_MAX];
__device__ int    g_conjRank[NF_MAX];
__device__ int    g_offA[NF_MAX];                   // cidx(v)*TPC + brev7(u)
__device__ int    g_offB[NF_MAX];
__device__ float2 g_A[61 * 3 * 4096];
__device__ float4 g_Xf4[(size_t)NF_MAX * 512];      // [f][i*16+b] /2
__device__ float2 g_YfT[(size_t)1024 * NF_MAX];     // [b*64+o][f]  (transposed!)
#define g_Xf ((float2*)g_Xf4)

typedef unsigned long long cplx;                    // packed (re, im) f32x2

__device__ __forceinline__ int brev7(int x) { return (int)(__brev((unsigned)x) >> 25); }

// ---------------- packed f32x2 complex helpers ----------------------------------
__device__ __forceinline__ cplx cpack(float x, float y){
    cplx r; asm("mov.b64 %0, {%1, %2};" : "=l"(r) : "f"(x), "f"(y)); return r;
}
__device__ __forceinline__ float clo(cplx a){
    float x; asm("{ .reg .f32 hi; mov.b64 {%0, hi}, %1; }" : "=f"(x) : "l"(a)); return x;
}
__device__ __forceinline__ float chi(cplx a){
    float y; asm("{ .reg .f32 lo; mov.b64 {lo, %0}, %1; }" : "=f"(y) : "l"(a)); return y;
}
__device__ __forceinline__ cplx cadd2(cplx a, cplx b){
    cplx r; asm("add.rn.f32x2 %0, %1, %2;" : "=l"(r) : "l"(a), "l"(b)); return r;
}
__device__ __forceinline__ cplx csub2(cplx a, cplx b){
    cplx r; asm("sub.rn.f32x2 %0, %1, %2;" : "=l"(r) : "l"(a), "l"(b)); return r;
}
__device__ __forceinline__ cplx cmul2(cplx a, cplx b){
    cplx r; asm("mul.rn.f32x2 %0, %1, %2;" : "=l"(r) : "l"(a), "l"(b)); return r;
}
__device__ __forceinline__ cplx cfma2(cplx a, cplx b, cplx c){
    cplx r; asm("fma.rn.f32x2 %0, %1, %2, %3;" : "=l"(r) : "l"(a), "l"(b), "l"(c)); return r;
}
__device__ __forceinline__ cplx cmulT(cplx b, float4 t){
    float bx = clo(b), by = chi(b);
    return cfma2(cpack(by, by), cpack(t.z, t.w), cmul2(cpack(bx, bx), cpack(t.x, t.y)));
}
__device__ __forceinline__ cplx cmulnegi(cplx a){
    float x = clo(a), y = chi(a); return cpack(y, -x);
}
__device__ __forceinline__ cplx cmulposi(cplx a){
    float x = clo(a), y = chi(a); return cpack(-y, x);
}

// ---------------- merged setup: prep_A (blocks 0..243) + init (blocks 244..259) --
__device__ __forceinline__ int vmaxOf(int rem){
    int vm = __float2int_rd(sqrtf((float)rem));
    while (vm*vm > rem) vm--;
    while ((vm+1)*(vm+1) <= rem) vm++;
    return vm;
}

__global__ __launch_bounds__(1024) void setup_kernel(const float* __restrict__ wgt){
    int blk = blockIdx.x, tid = threadIdx.x;
    if (blk < 244){
        __shared__ float2 se1, se2;
        int c = blk >> 2;
        if (tid == 0){
            int v = (c <= 30) ? c : c + 67;
            double a1 = -6.283185307179586476925286766559 * (double)v / 128.0;
            double a2 = -6.283185307179586476925286766559 * (double)((2*v) & 127) / 128.0;
            se1 = make_float2((float)cos(a1), (float)sin(a1));
            se2 = make_float2((float)cos(a2), (float)sin(a2));
        }
        __syncthreads();
        float2 e1 = se1, e2 = se2;
        int oi = ((blk & 3) << 10) + tid;
        const float* w9 = wgt + oi*9;
        #pragma unroll
        for (int p = 0; p < 3; p++){
            float w0 = w9[p*3], w1 = w9[p*3+1], w2 = w9[p*3+2];
            float2 acc;
            acc.x = w0 + w1*e1.x + w2*e2.x;
            acc.y =      w1*e1.y + w2*e2.y;
            g_A[((size_t)c*3 + p)*4096 + oi] = acc;
        }
    } else {
        __shared__ int rowBase[128];
        __shared__ int vmax[128];
        int ib = blk - 244;
        if (ib == 0 && tid <= 32){
            double ang = -6.283185307179586476925286766559 * (double)tid / 128.0;
            float c = (float)cos(ang), s = (float)sin(ang);
            if (tid == 0)      { g_E[0]  = make_float2(1.f, 0.f);  g_E[64] = make_float2(-1.f, 0.f); }
            else if (tid == 32){ g_E[32] = make_float2(0.f, -1.f); g_E[96] = make_float2(0.f, 1.f); }
            else {
                g_E[tid]       = make_float2( c,  s);
                g_E[64 - tid]  = make_float2(-c,  s);
                g_E[64 + tid]  = make_float2(-c, -s);
                g_E[128 - tid] = make_float2( c, -s);
            }
        }
        if (tid < 128){
            int du = (tid < 64) ? tid : tid - 128;
            int rem = 900 - du*du;
            vmax[tid] = (rem >= 0) ? vmaxOf(rem) : -1;
        }
        __syncthreads();
        if (tid == 0){
            int s = 0;
            for (int u = 0; u < 128; u++){ rowBase[u] = s; if (vmax[u] >= 0) s += 2*vmax[u] + 1; }
        }
        __syncthreads();
        int t = ib * 1024 + tid;
        if (t < 16384){
            int u = t >> 7, v = t & 127;
            int vm = vmax[u];
            if (vm >= 0){
                int dv = (v < 64) ? v : v - 128;
                if (dv >= -vm && dv <= vm){
                    int r = rowBase[u] + ((v <= vm) ? v : v - (128 - vm) + vm + 1);
                    int uc = (128 - u) & 127, vc = (128 - v) & 127;
                    int vmc = vmax[uc];
                    int rc = rowBase[uc] + ((vc <= vmc) ? vc : vc - (128 - vmc) + vmc + 1);
                    int cA = (v  <= 30) ? v  : v  - 67;
                    int cB = (vc <= 30) ? vc : vc - 67;
                    g_maskUV[r]   = t;
                    g_conjRank[r] = rc;
                    g_offA[r]     = cA*TPC + brev7(u);
                    g_offB[r]     = cB*TPC + brev7(uc);
                }
            }
        }
    }
}

// ---------------- packed radix bodies -------------------------------------------
__device__ __forceinline__ void dif8_body(cplx* d, const float4* t4, int base, int stp, int j){
    cplx x[8];
    #pragma unroll
    for (int m = 0; m < 8; m++) x[m] = d[base + m*stp];
    #pragma unroll
    for (int m = 0; m < 4; m++){
        cplx a = x[m], b = x[m+4];
        x[m] = cadd2(a,b); x[m+4] = cmulT(csub2(a,b), t4[j + 16*m]);
    }
    {
        float4 w0 = t4[2*j], w1 = t4[2*j + 32]; cplx a, b;
        a=x[0]; b=x[2]; x[0]=cadd2(a,b); x[2]=cmulT(csub2(a,b), w0);
        a=x[1]; b=x[3]; x[1]=cadd2(a,b); x[3]=cmulT(csub2(a,b), w1);
        a=x[4]; b=x[6]; x[4]=cadd2(a,b); x[6]=cmulT(csub2(a,b), w0);
        a=x[5]; b=x[7]; x[5]=cadd2(a,b); x[7]=cmulT(csub2(a,b), w1);
    }
    {
        float4 w = t4[4*j];
        #pragma unroll
        for (int m = 0; m < 8; m += 2){
            cplx a = x[m], b = x[m+1];
            x[m] = cadd2(a,b); x[m+1] = cmulT(csub2(a,b), w);
        }
    }
    #pragma unroll
    for (int m = 0; m < 8; m++) d[base + m*stp] = x[m];
}

__device__ __forceinline__ void dif16_core(cplx* x, const float4* t4){
    #pragma unroll
    for (int m = 0; m < 8; m++){
        cplx a = x[m], b = x[m+8];
        x[m] = cadd2(a,b); x[m+8] = cmulT(csub2(a,b), t4[8*m]);
    }
    #pragma unroll
    for (int m = 0; m < 4; m++){
        float4 w = t4[16*m]; cplx a, b;
        a=x[m];   b=x[m+4];  x[m]  =cadd2(a,b); x[m+4] =cmulT(csub2(a,b), w);
        a=x[m+8]; b=x[m+12]; x[m+8]=cadd2(a,b); x[m+12]=cmulT(csub2(a,b), w);
    }
    #pragma unroll
    for (int g = 0; g < 4; g++){
        int b0 = 4*g; cplx a, b;
        a=x[b0];   b=x[b0+2]; x[b0]  =cadd2(a,b); x[b0+2]=csub2(a,b);
        a=x[b0+1]; b=x[b0+3]; x[b0+1]=cadd2(a,b); x[b0+3]=cmulnegi(csub2(a,b));
    }
    #pragma unroll
    for (int m = 0; m < 16; m += 2){
        cplx a = x[m], b = x[m+1];
        x[m] = cadd2(a,b); x[m+1] = csub2(a,b);
    }
}

__device__ __forceinline__ void dif16_body(cplx* d, const float4* t4, int base, int es){
    cplx x[16];
    #pragma unroll
    for (int m = 0; m < 16; m++) x[m] = d[base + m*es];
    dif16_core(x, t4);
    #pragma unroll
    for (int m = 0; m < 16; m++) d[base + m*es] = x[m];
}

__device__ __forceinline__ void dit16_core(cplx* x, const float4* t4){
    #pragma unroll
    for (int m = 0; m < 16; m += 2){
        cplx a = x[m], b = x[m+1];
        x[m] = cadd2(a,b); x[m+1] = csub2(a,b);
    }
    #pragma unroll
    for (int g = 0; g < 4; g++){
        int b0 = 4*g; cplx a, tt;
        a=x[b0];   tt=x[b0+2];           x[b0]  =cadd2(a,tt); x[b0+2]=csub2(a,tt);
        a=x[b0+1]; tt=cmulposi(x[b0+3]); x[b0+1]=cadd2(a,tt); x[b0+3]=csub2(a,tt);
    }
    #pragma unroll
    for (int m = 0; m < 4; m++){
        float4 w = t4[16*m]; cplx a, tt;
        a=x[m];   tt=cmulT(x[m+4],  w); x[m]  =cadd2(a,tt); x[m+4] =csub2(a,tt);
        a=x[m+8]; tt=cmulT(x[m+12], w); x[m+8]=cadd2(a,tt); x[m+12]=csub2(a,tt);
    }
    #pragma unroll
    for (int m = 0; m < 8; m++){
        cplx a = x[m], tt = cmulT(x[m+8], t4[8*m]);
        x[m] = cadd2(a,tt); x[m+8] = csub2(a,tt);
    }
}

__device__ __forceinline__ void dit16_body(cplx* d, const float4* t4, int base, int es){
    cplx x[16];
    #pragma unroll
    for (int m = 0; m < 16; m++) x[m] = d[base + m*es];
    dit16_core(x, t4);
    #pragma unroll
    for (int m = 0; m < 16; m++) d[base + m*es] = x[m];
}

__device__ __forceinline__ void dit8_body(cplx* d, const float4* t4, int base, int stp, int j){
    cplx x[8];
    #pragma unroll
    for (int m = 0; m < 8; m++) x[m] = d[base + m*stp];
    {
        float4 w = t4[4*j];
        #pragma unroll
        for (int m = 0; m < 8; m += 2){
            cplx a = x[m], tt = cmulT(x[m+1], w);
            x[m] = cadd2(a,tt); x[m+1] = csub2(a,tt);
        }
    }
    {
        float4 w0 = t4[2*j], w1 = t4[2*j + 32]; cplx a, tt;
        a=x[0]; tt=cmulT(x[2], w0); x[0]=cadd2(a,tt); x[2]=csub2(a,tt);
        a=x[1]; tt=cmulT(x[3], w1); x[1]=cadd2(a,tt); x[3]=csub2(a,tt);
        a=x[4]; tt=cmulT(x[6], w0); x[4]=cadd2(a,tt); x[6]=csub2(a,tt);
        a=x[5]; tt=cmulT(x[7], w1); x[5]=cadd2(a,tt); x[7]=csub2(a,tt);
    }
    #pragma unroll
    for (int m = 0; m < 4; m++){
        cplx a = x[m], tt = cmulT(x[m+4], t4[j + 16*m]);
        x[m] = cadd2(a,tt); x[m+4] = csub2(a,tt);
    }
    #pragma unroll
    for (int m = 0; m < 8; m++) d[base + m*stp] = x[m];
}

__device__ __constant__ int V16[16] = {0,64,32,96,16,80,48,112,8,72,40,104,24,88,56,120};

// ---------------- forward -------------------------------------------------------
__global__ __launch_bounds__(384, 2) void fwd_kernel(const float* __restrict__ x, int nMask){
    extern __shared__ cplx smemBuf[];
    cplx* ctile = smemBuf;
    cplx* stg   = smemBuf + CTILE_CPLX;
    __shared__ float4 tw4[64];
    int tid = threadIdx.x, lane = tid & 31, wid = tid >> 5;
    if (tid < 64){ float2 e = g_E[tid]; tw4[tid] = make_float4(e.x, e.y, -e.y, e.x); }
    int b = blockIdx.x >> 5, ip = blockIdx.x & 31;
    int i0 = 2*ip;
    const float* s0 = x + (size_t)(b*64 + i0) * 16384;
    const float* s1 = s0 + 16384;
    __syncthreads();

    cplx* wst = stg + wid*2*SPITCH;
    for (int pr = wid; pr < 64; pr += 12){
        #pragma unroll
        for (int rr = 0; rr < 2; rr++){
            int row = 2*pr + rr;
            float4 a = ((const float4*)(s0 + row*128))[lane];
            float4 c = ((const float4*)(s1 + row*128))[lane];
            cplx* dst = wst + rr*SPITCH + 4*lane + (lane >> 2);
            dst[0] = cpack(a.x, c.x);
            dst[1] = cpack(a.y, c.y);
            dst[2] = cpack(a.z, c.z);
            dst[3] = cpack(a.w, c.w);
        }
        __syncwarp();
        {   int rr = lane >> 4, j = lane & 15;
            dif8_body(wst, tw4, rr*SPITCH + j, 17, j); }
        __syncwarp();
        if (lane < 16){
            int rr = lane >> 3, blk = lane & 7;
            int row = 2*pr + rr;
            int rb = ((blk & 1) << 2) | (blk & 2) | (blk >> 2);
            cplx xv[16];
            cplx* src = wst + rr*SPITCH + blk*17;
            #pragma unroll
            for (int m = 0; m < 16; m++) xv[m] = src[m];
            dif16_core(xv, tw4);
            #pragma unroll
            for (int m = 0; m < 16; m++){
                int v = V16[m] + rb;
                if (v <= 30)       ctile[v*TPC + row]        = xv[m];
                else if (v >= 98)  ctile[(v - 67)*TPC + row] = xv[m];
            }
        }
        __syncwarp();
    }
    __syncthreads();

    for (int t = tid; t < 1024; t += 384){
        int j = t & 15, c = t >> 4;
        dif8_body(ctile, tw4, c*TPC + j, 16, j);
    }
    __syncthreads();
    for (int t = tid; t < 512; t += 384){
        int c = t & 63, blk = t >> 6;
        dif16_body(ctile, tw4, c*TPC + blk*16, 1);
    }
    __syncthreads();

    float2* ct2 = (float2*)ctile;
    for (int f = tid; f < nMask; f += 384){
        int pr = g_conjRank[f];
        if (pr < f) continue;
        float2 z  = ct2[g_offA[f]];
        float2 zc = ct2[g_offB[f]];
        float2 X0 = make_float2(0.5f*(z.x + zc.x), 0.5f*(z.y - zc.y));
        float2 X1 = make_float2(0.5f*(z.y + zc.y), 0.5f*(zc.x - z.x));
        size_t base = (size_t)f*1024 + i0*16 + b;
        g_Xf[base]      = X0;
        g_Xf[base + 16] = X1;
    }
}

// ---------------- per-frequency channel mix -------------------------------------
__global__ __launch_bounds__(256) void mix_kernel(int nMask){
    __shared__ float Xre[1024];
    __shared__ float Xim[1024];
    __shared__ float2 Ws[64 * 65];   // [i][o]
    int f = blockIdx.x;
    int pr = g_conjRank[f];
    if (pr < f) return;
    int tid = threadIdx.x;
    int uv = g_maskUV[f];
    int u = uv >> 7, v = uv & 127;
    int c = (v <= 30) ? v : v - 67;
    float2 eu1 = g_E[u], eu2 = g_E[(2*u) & 127];
    for (int j = tid; j < 512; j += 256){
        float4 q = g_Xf4[(size_t)f*512 + j];
        int b2 = j*2;
        Xre[b2]   = q.x;  Xim[b2]   = q.y;
        Xre[b2+1] = q.z;  Xim[b2+1] = q.w;
    }
    const float2* Ac = g_A + (size_t)c*3*4096;
    for (int oi = tid; oi < 4096; oi += 256){
        float2 a0 = Ac[oi], a1 = Ac[oi + 4096], a2 = Ac[oi + 8192];
        float2 wv;
        wv.x = a0.x + a1.x*eu1.x - a1.y*eu1.y + a2.x*eu2.x - a2.y*eu2.y;
        wv.y = a0.y + a1.x*eu1.y + a1.y*eu1.x + a2.x*eu2.y + a2.y*eu2.x;
        Ws[(oi & 63)*65 + (oi >> 6)] = wv;
    }
    __syncthreads();
    int o  = tid & 63;
    int bb = (tid >> 6) << 2;
    cplx ax01 = cpack(0.f,0.f), ax23 = ax01, ay01 = ax01, ay23 = ax01;
    #pragma unroll 8
    for (int i = 0; i < 64; i++){
        float2 w = Ws[i*65 + o];
        cplx wx2  = cpack(w.x,  w.x);
        cplx wy2  = cpack(w.y,  w.y);
        cplx wny2 = cpack(-w.y, -w.y);
        float4 r4 = *(const float4*)&Xre[i*16 + bb];
        float4 m4 = *(const float4*)&Xim[i*16 + bb];
        cplx re01 = cpack(r4.x, r4.y), re23 = cpack(r4.z, r4.w);
        cplx im01 = cpack(m4.x, m4.y), im23 = cpack(m4.z, m4.w);
        ax01 = cfma2(re01, wx2,  ax01);  ax01 = cfma2(im01, wny2, ax01);
        ax23 = cfma2(re23, wx2,  ax23);  ax23 = cfma2(im23, wny2, ax23);
        ay01 = cfma2(re01, wy2,  ay01);  ay01 = cfma2(im01, wx2,  ay01);
        ay23 = cfma2(re23, wy2,  ay23);  ay23 = cfma2(im23, wx2,  ay23);
    }
    float2 a0 = make_float2(clo(ax01), clo(ay01));
    float2 a1 = make_float2(chi(ax01), chi(ay01));
    float2 a2 = make_float2(clo(ax23), clo(ay23));
    float2 a3 = make_float2(chi(ax23), chi(ay23));
    // transposed writes: g_YfT[(b*64+o)][f]
    size_t r0 = (size_t)((bb+0)*64 + o)*NF_MAX;
    size_t r1 = (size_t)((bb+1)*64 + o)*NF_MAX;
    size_t r2 = (size_t)((bb+2)*64 + o)*NF_MAX;
    size_t r3 = (size_t)((bb+3)*64 + o)*NF_MAX;
    g_YfT[r0 + f] = a0;
    g_YfT[r1 + f] = a1;
    g_YfT[r2 + f] = a2;
    g_YfT[r3 + f] = a3;
    if (pr != f){
        g_YfT[r0 + pr] = make_float2(a0.x, -a0.y);
        g_YfT[r1 + pr] = make_float2(a1.x, -a1.y);
        g_YfT[r2 + pr] = make_float2(a2.x, -a2.y);
        g_YfT[r3 + pr] = make_float2(a3.x, -a3.y);
    }
}

// ---------------- inverse -------------------------------------------------------
__global__ __launch_bounds__(384, 2) void inv_kernel(float* __restrict__ out,
                                                     const float* __restrict__ bias, int nMask){
    extern __shared__ cplx smemBuf[];
    cplx* ctile = smemBuf;
    cplx* stg   = smemBuf + CTILE_CPLX;
    __shared__ float4 tw4[64];
    int tid = threadIdx.x, lane = tid & 31, wid = tid >> 5;
    if (tid < 64){ float2 e = g_E[tid]; tw4[tid] = make_float4(e.x, -e.y, e.y, e.x); }
    int b = blockIdx.x >> 5, op = blockIdx.x & 31;
    int o0 = 2*op;
    int bsrc = (b + 8) & 15;
    int osrc = (o0 + 32) & 63;
    {
        float4 z4 = make_float4(0.f, 0.f, 0.f, 0.f);
        float4* d4 = (float4*)ctile;
        for (int t = tid; t < CTILE_CPLX/2; t += 384) d4[t] = z4;
    }
    __syncthreads();

    // coalesced reads of two contiguous rows; Z = Y0 + i*Y1
    float2* ct2 = (float2*)ctile;
    const float2* y0row = g_YfT + (size_t)(bsrc*64 + osrc)*NF_MAX;
    const float2* y1row = y0row + NF_MAX;
    for (int f = tid; f < nMask; f += 384){
        float2 y0 = y0row[f];
        float2 y1 = y1row[f];
        ct2[g_offA[f]] = make_float2(y0.x - y1.y, y0.y + y1.x);
    }
    __syncthreads();

    for (int t = tid; t < 512; t += 384){
        int c = t & 63, blk = t >> 6;
        dit16_body(ctile, tw4, c*TPC + blk*16, 1);
    }
    __syncthreads();
    for (int t = tid; t < 1024; t += 384){
        int j = t & 15, c = t >> 4;
        dit8_body(ctile, tw4, c*TPC + j, 16, j);
    }
    __syncthreads();

    float bv0 = bias[o0], bv1 = bias[o0 + 1];
    float* d0 = out + (size_t)(b*64 + o0) * 16384;
    float* d1 = d0 + 16384;
    const float sc = 1.f / 16384.f;
    cplx* wst = stg + wid*2*SPITCH;
    cplx zero = cpack(0.f, 0.f);
    for (int pr = wid; pr < 64; pr += 12){
        if (lane < 16){
            int rr = lane >> 3, blk = lane & 7;
            int row = 2*pr + rr;
            int rb = ((blk & 1) << 2) | (blk & 2) | (blk >> 2);
            cplx xv[16];
            #pragma unroll
            for (int m = 0; m < 16; m++){
                int v = V16[m] + rb;
                cplx val = zero;
                if (v <= 30)      val = ctile[v*TPC + row];
                else if (v >= 98) val = ctile[(v - 67)*TPC + row];
                xv[m] = val;
            }
            dit16_core(xv, tw4);
            cplx* dst = wst + rr*SPITCH + blk*17;
            #pragma unroll
            for (int m = 0; m < 16; m++) dst[m] = xv[m];
        }
        __syncwarp();
        {   int rr = lane >> 4, j = lane & 15;
            dit8_body(wst, tw4, rr*SPITCH + j, 17, j); }
        __syncwarp();
        #pragma unroll
        for (int rr = 0; rr < 2; rr++){
            int row = 2*pr + rr;
            const cplx* src = wst + rr*SPITCH + 4*lane + (lane >> 2);
            cplx w0 = src[0], w1 = src[1], w2 = src[2], w3 = src[3];
            ((float4*)(d0 + row*128))[lane] =
                make_float4(clo(w0)*sc + bv0, clo(w1)*sc + bv0, clo(w2)*sc + bv0, clo(w3)*sc + bv0);
            ((float4*)(d1 + row*128))[lane] =
                make_float4(chi(w0)*sc + bv1, chi(w1)*sc + bv1, chi(w2)*sc + bv1, chi(w3)*sc + bv1);
        }
        __syncwarp();
    }
}

// ---------------- launch --------------------------------------------------------
extern "C" void kernel_launch(void* const* d_in, const int* in_sizes, int n_in,
                              void* d_out, int out_size){
    const float* x    = (const float*)d_in[0];
    const float* wgt  = (const float*)d_in[1];
    const float* bias = (const float*)d_in[2];
    float* out = (float*)d_out;

    int nMask = 0;
    for (int u = 0; u < 128; u++){
        int du = (u < 64) ? u : u - 128;
        for (int v = 0; v < 128; v++){
            int dv = (v < 64) ? v : v - 128;
            if (du*du + dv*dv <= 900) nMask++;
        }
    }

    cudaFuncSetAttribute(fwd_kernel, cudaFuncAttributeMaxDynamicSharedMemorySize, (int)SMEM_BYTES);
    cudaFuncSetAttribute(inv_kernel, cudaFuncAttributeMaxDynamicSharedMemorySize, (int)SMEM_BYTES);

    setup_kernel<<<260, 1024>>>(wgt);
    fwd_kernel<<<512, 384, SMEM_BYTES>>>(x, nMask);
    mix_kernel<<<nMask, 256>>>(nMask);
    inv_kernel<<<512, 384, SMEM_BYTES>>>(out, bias, nMask);
}

// round 14
// speedup vs baseline: 1.0288x; 1.0288x over previous
#include <cuda_runtime.h>

#define TPC 129                                     // compact tile pitch (h dim)
#define SPITCH 136                                  // padded staging row pitch (128 + 8)
#define NF_MAX 2850
#define CTILE_CPLX (64 * TPC)                       // 8256 cplx
#define STG_CPLX   (12 * 2 * SPITCH)                // 3264 cplx
#define SMEM_BYTES ((CTILE_CPLX + STG_CPLX) * 8)    // 92160 B

// ---------------- device scratch ------------------------------------------------
__device__ float2 g_E[128];
__device__ int    g_maskUV[NF_MAX];
__device__ int    g_conjRank[NF_MAX];
__device__ int    g_offA[NF_MAX];                   // cidx(v)*TPC + brev7(u)
__device__ int    g_offB[NF_MAX];
__device__ float2 g_A[61 * 3 * 4096];
__device__ float4 g_Xf4[(size_t)NF_MAX * 512];      // [f][i*16+b] /2
__device__ float2 g_Yz [(size_t)NF_MAX * 512];      // [f][b*32+zo]  Z-packed spectrum
__device__ float2 g_YzT[(size_t)512 * NF_MAX];      // [b*32+zo][f]  transposed
#define g_Xf ((float2*)g_Xf4)

typedef unsigned long long cplx;                    // packed (re, im) f32x2

__device__ __forceinline__ int brev7(int x) { return (int)(__brev((unsigned)x) >> 25); }

// ---------------- packed f32x2 complex helpers ----------------------------------
__device__ __forceinline__ cplx cpack(float x, float y){
    cplx r; asm("mov.b64 %0, {%1, %2};" : "=l"(r) : "f"(x), "f"(y)); return r;
}
__device__ __forceinline__ float clo(cplx a){
    float x; asm("{ .reg .f32 hi; mov.b64 {%0, hi}, %1; }" : "=f"(x) : "l"(a)); return x;
}
__device__ __forceinline__ float chi(cplx a){
    float y; asm("{ .reg .f32 lo; mov.b64 {lo, %0}, %1; }" : "=f"(y) : "l"(a)); return y;
}
__device__ __forceinline__ cplx cadd2(cplx a, cplx b){
    cplx r; asm("add.rn.f32x2 %0, %1, %2;" : "=l"(r) : "l"(a), "l"(b)); return r;
}
__device__ __forceinline__ cplx csub2(cplx a, cplx b){
    cplx r; asm("sub.rn.f32x2 %0, %1, %2;" : "=l"(r) : "l"(a), "l"(b)); return r;
}
__device__ __forceinline__ cplx cmul2(cplx a, cplx b){
    cplx r; asm("mul.rn.f32x2 %0, %1, %2;" : "=l"(r) : "l"(a), "l"(b)); return r;
}
__device__ __forceinline__ cplx cfma2(cplx a, cplx b, cplx c){
    cplx r; asm("fma.rn.f32x2 %0, %1, %2, %3;" : "=l"(r) : "l"(a), "l"(b), "l"(c)); return r;
}
__device__ __forceinline__ cplx cmulT(cplx b, float4 t){
    float bx = clo(b), by = chi(b);
    return cfma2(cpack(by, by), cpack(t.z, t.w), cmul2(cpack(bx, bx), cpack(t.x, t.y)));
}
__device__ __forceinline__ cplx cmulnegi(cplx a){
    float x = clo(a), y = chi(a); return cpack(y, -x);
}
__device__ __forceinline__ cplx cmulposi(cplx a){
    float x = clo(a), y = chi(a); return cpack(-y, x);
}

// ---------------- merged setup: prep_A (blocks 0..243) + init (blocks 244..259) --
__device__ __forceinline__ int vmaxOf(int rem){
    int vm = __float2int_rd(sqrtf((float)rem));
    while (vm*vm > rem) vm--;
    while ((vm+1)*(vm+1) <= rem) vm++;
    return vm;
}

__global__ __launch_bounds__(1024) void setup_kernel(const float* __restrict__ wgt){
    int blk = blockIdx.x, tid = threadIdx.x;
    if (blk < 244){
        __shared__ float2 se1, se2;
        int c = blk >> 2;
        if (tid == 0){
            int v = (c <= 30) ? c : c + 67;
            double a1 = -6.283185307179586476925286766559 * (double)v / 128.0;
            double a2 = -6.283185307179586476925286766559 * (double)((2*v) & 127) / 128.0;
            se1 = make_float2((float)cos(a1), (float)sin(a1));
            se2 = make_float2((float)cos(a2), (float)sin(a2));
        }
        __syncthreads();
        float2 e1 = se1, e2 = se2;
        int oi = ((blk & 3) << 10) + tid;
        const float* w9 = wgt + oi*9;
        #pragma unroll
        for (int p = 0; p < 3; p++){
            float w0 = w9[p*3], w1 = w9[p*3+1], w2 = w9[p*3+2];
            float2 acc;
            acc.x = w0 + w1*e1.x + w2*e2.x;
            acc.y =      w1*e1.y + w2*e2.y;
            g_A[((size_t)c*3 + p)*4096 + oi] = acc;
        }
    } else {
        __shared__ int rowBase[128];
        __shared__ int vmax[128];
        int ib = blk - 244;
        if (ib == 0 && tid <= 32){
            double ang = -6.283185307179586476925286766559 * (double)tid / 128.0;
            float c = (float)cos(ang), s = (float)sin(ang);
            if (tid == 0)      { g_E[0]  = make_float2(1.f, 0.f);  g_E[64] = make_float2(-1.f, 0.f); }
            else if (tid == 32){ g_E[32] = make_float2(0.f, -1.f); g_E[96] = make_float2(0.f, 1.f); }
            else {
                g_E[tid]       = make_float2( c,  s);
                g_E[64 - tid]  = make_float2(-c,  s);
                g_E[64 + tid]  = make_float2(-c, -s);
                g_E[128 - tid] = make_float2( c, -s);
            }
        }
        if (tid < 128){
            int du = (tid < 64) ? tid : tid - 128;
            int rem = 900 - du*du;
            vmax[tid] = (rem >= 0) ? vmaxOf(rem) : -1;
        }
        __syncthreads();
        if (tid == 0){
            int s = 0;
            for (int u = 0; u < 128; u++){ rowBase[u] = s; if (vmax[u] >= 0) s += 2*vmax[u] + 1; }
        }
        __syncthreads();
        int t = ib * 1024 + tid;
        if (t < 16384){
            int u = t >> 7, v = t & 127;
            int vm = vmax[u];
            if (vm >= 0){
                int dv = (v < 64) ? v : v - 128;
                if (dv >= -vm && dv <= vm){
                    int r = rowBase[u] + ((v <= vm) ? v : v - (128 - vm) + vm + 1);
                    int uc = (128 - u) & 127, vc = (128 - v) & 127;
                    int vmc = vmax[uc];
                    int rc = rowBase[uc] + ((vc <= vmc) ? vc : vc - (128 - vmc) + vmc + 1);
                    int cA = (v  <= 30) ? v  : v  - 67;
                    int cB = (vc <= 30) ? vc : vc - 67;
                    g_maskUV[r]   = t;
                    g_conjRank[r] = rc;
                    g_offA[r]     = cA*TPC + brev7(u);
                    g_offB[r]     = cB*TPC + brev7(uc);
                }
            }
        }
    }
}

// ---------------- packed radix bodies -------------------------------------------
__device__ __forceinline__ void dif8_body(cplx* d, const float4* t4, int base, int stp, int j){
    cplx x[8];
    #pragma unroll
    for (int m = 0; m < 8; m++) x[m] = d[base + m*stp];
    #pragma unroll
    for (int m = 0; m < 4; m++){
        cplx a = x[m], b = x[m+4];
        x[m] = cadd2(a,b); x[m+4] = cmulT(csub2(a,b), t4[j + 16*m]);
    }
    {
        float4 w0 = t4[2*j], w1 = t4[2*j + 32]; cplx a, b;
        a=x[0]; b=x[2]; x[0]=cadd2(a,b); x[2]=cmulT(csub2(a,b), w0);
        a=x[1]; b=x[3]; x[1]=cadd2(a,b); x[3]=cmulT(csub2(a,b), w1);
        a=x[4]; b=x[6]; x[4]=cadd2(a,b); x[6]=cmulT(csub2(a,b), w0);
        a=x[5]; b=x[7]; x[5]=cadd2(a,b); x[7]=cmulT(csub2(a,b), w1);
    }
    {
        float4 w = t4[4*j];
        #pragma unroll
        for (int m = 0; m < 8; m += 2){
            cplx a = x[m], b = x[m+1];
            x[m] = cadd2(a,b); x[m+1] = cmulT(csub2(a,b), w);
        }
    }
    #pragma unroll
    for (int m = 0; m < 8; m++) d[base + m*stp] = x[m];
}

__device__ __forceinline__ void dif16_core(cplx* x, const float4* t4){
    #pragma unroll
    for (int m = 0; m < 8; m++){
        cplx a = x[m], b = x[m+8];
        x[m] = cadd2(a,b); x[m+8] = cmulT(csub2(a,b), t4[8*m]);
    }
    #pragma unroll
    for (int m = 0; m < 4; m++){
        float4 w = t4[16*m]; cplx a, b;
        a=x[m];   b=x[m+4];  x[m]  =cadd2(a,b); x[m+4] =cmulT(csub2(a,b), w);
        a=x[m+8]; b=x[m+12]; x[m+8]=cadd2(a,b); x[m+12]=cmulT(csub2(a,b), w);
    }
    #pragma unroll
    for (int g = 0; g < 4; g++){
        int b0 = 4*g; cplx a, b;
        a=x[b0];   b=x[b0+2]; x[b0]  =cadd2(a,b); x[b0+2]=csub2(a,b);
        a=x[b0+1]; b=x[b0+3]; x[b0+1]=cadd2(a,b); x[b0+3]=cmulnegi(csub2(a,b));
    }
    #pragma unroll
    for (int m = 0; m < 16; m += 2){
        cplx a = x[m], b = x[m+1];
        x[m] = cadd2(a,b); x[m+1] = csub2(a,b);
    }
}

__device__ __forceinline__ void dif16_body(cplx* d, const float4* t4, int base, int es){
    cplx x[16];
    #pragma unroll
    for (int m = 0; m < 16; m++) x[m] = d[base + m*es];
    dif16_core(x, t4);
    #pragma unroll
    for (int m = 0; m < 16; m++) d[base + m*es] = x[m];
}

__device__ __forceinline__ void dit16_core(cplx* x, const float4* t4){
    #pragma unroll
    for (int m = 0; m < 16; m += 2){
        cplx a = x[m], b = x[m+1];
        x[m] = cadd2(a,b); x[m+1] = csub2(a,b);
    }
    #pragma unroll
    for (int g = 0; g < 4; g++){
        int b0 = 4*g; cplx a, tt;
        a=x[b0];   tt=x[b0+2];           x[b0]  =cadd2(a,tt); x[b0+2]=csub2(a,tt);
        a=x[b0+1]; tt=cmulposi(x[b0+3]); x[b0+1]=cadd2(a,tt); x[b0+3]=csub2(a,tt);
    }
    #pragma unroll
    for (int m = 0; m < 4; m++){
        float4 w = t4[16*m]; cplx a, tt;
        a=x[m];   tt=cmulT(x[m+4],  w); x[m]  =cadd2(a,tt); x[m+4] =csub2(a,tt);
        a=x[m+8]; tt=cmulT(x[m+12], w); x[m+8]=cadd2(a,tt); x[m+12]=csub2(a,tt);
    }
    #pragma unroll
    for (int m = 0; m < 8; m++){
        cplx a = x[m], tt = cmulT(x[m+8], t4[8*m]);
        x[m] = cadd2(a,tt); x[m+8] = csub2(a,tt);
    }
}

__device__ __forceinline__ void dit16_body(cplx* d, const float4* t4, int base, int es){
    cplx x[16];
    #pragma unroll
    for (int m = 0; m < 16; m++) x[m] = d[base + m*es];
    dit16_core(x, t4);
    #pragma unroll
    for (int m = 0; m < 16; m++) d[base + m*es] = x[m];
}

__device__ __forceinline__ void dit8_body(cplx* d, const float4* t4, int base, int stp, int j){
    cplx x[8];
    #pragma unroll
    for (int m = 0; m < 8; m++) x[m] = d[base + m*stp];
    {
        float4 w = t4[4*j];
        #pragma unroll
        for (int m = 0; m < 8; m += 2){
            cplx a = x[m], tt = cmulT(x[m+1], w);
            x[m] = cadd2(a,tt); x[m+1] = csub2(a,tt);
        }
    }
    {
        float4 w0 = t4[2*j], w1 = t4[2*j + 32]; cplx a, tt;
        a=x[0]; tt=cmulT(x[2], w0); x[0]=cadd2(a,tt); x[2]=csub2(a,tt);
        a=x[1]; tt=cmulT(x[3], w1); x[1]=cadd2(a,tt); x[3]=csub2(a,tt);
        a=x[4]; tt=cmulT(x[6], w0); x[4]=cadd2(a,tt); x[6]=csub2(a,tt);
        a=x[5]; tt=cmulT(x[7], w1); x[5]=cadd2(a,tt); x[7]=csub2(a,tt);
    }
    #pragma unroll
    for (int m = 0; m < 4; m++){
        cplx a = x[m], tt = cmulT(x[m+4], t4[j + 16*m]);
        x[m] = cadd2(a,tt); x[m+4] = csub2(a,tt);
    }
    #pragma unroll
    for (int m = 0; m < 8; m++) d[base + m*stp] = x[m];
}

__device__ __constant__ int V16[16] = {0,64,32,96,16,80,48,112,8,72,40,104,24,88,56,120};

// ---------------- forward -------------------------------------------------------
__global__ __launch_bounds__(384, 2) void fwd_kernel(const float* __restrict__ x, int nMask){
    extern __shared__ cplx smemBuf[];
    cplx* ctile = smemBuf;
    cplx* stg   = smemBuf + CTILE_CPLX;
    __shared__ float4 tw4[64];
    int tid = threadIdx.x, lane = tid & 31, wid = tid >> 5;
    if (tid < 64){ float2 e = g_E[tid]; tw4[tid] = make_float4(e.x, e.y, -e.y, e.x); }
    int b = blockIdx.x >> 5, ip = blockIdx.x & 31;
    int i0 = 2*ip;
    const float* s0 = x + (size_t)(b*64 + i0) * 16384;
    const float* s1 = s0 + 16384;
    __syncthreads();

    cplx* wst = stg + wid*2*SPITCH;
    for (int pr = wid; pr < 64; pr += 12){
        #pragma unroll
        for (int rr = 0; rr < 2; rr++){
            int row = 2*pr + rr;
            float4 a = ((const float4*)(s0 + row*128))[lane];
            float4 c = ((const float4*)(s1 + row*128))[lane];
            cplx* dst = wst + rr*SPITCH + 4*lane + (lane >> 2);
            dst[0] = cpack(a.x, c.x);
            dst[1] = cpack(a.y, c.y);
            dst[2] = cpack(a.z, c.z);
            dst[3] = cpack(a.w, c.w);
        }
        __syncwarp();
        {   int rr = lane >> 4, j = lane & 15;
            dif8_body(wst, tw4, rr*SPITCH + j, 17, j); }
        __syncwarp();
        if (lane < 16){
            int rr = lane >> 3, blk = lane & 7;
            int row = 2*pr + rr;
            int rb = ((blk & 1) << 2) | (blk & 2) | (blk >> 2);
            cplx xv[16];
            cplx* src = wst + rr*SPITCH + blk*17;
            #pragma unroll
            for (int m = 0; m < 16; m++) xv[m] = src[m];
            dif16_core(xv, tw4);
            #pragma unroll
            for (int m = 0; m < 16; m++){
                int v = V16[m] + rb;
                if (v <= 30)       ctile[v*TPC + row]        = xv[m];
                else if (v >= 98)  ctile[(v - 67)*TPC + row] = xv[m];
            }
        }
        __syncwarp();
    }
    __syncthreads();

    for (int t = tid; t < 1024; t += 384){
        int j = t & 15, c = t >> 4;
        dif8_body(ctile, tw4, c*TPC + j, 16, j);
    }
    __syncthreads();
    for (int t = tid; t < 512; t += 384){
        int c = t & 63, blk = t >> 6;
        dif16_body(ctile, tw4, c*TPC + blk*16, 1);
    }
    __syncthreads();

    float2* ct2 = (float2*)ctile;
    for (int f = tid; f < nMask; f += 384){
        int pr = g_conjRank[f];
        if (pr < f) continue;
        float2 z  = ct2[g_offA[f]];
        float2 zc = ct2[g_offB[f]];
        float2 X0 = make_float2(0.5f*(z.x + zc.x), 0.5f*(z.y - zc.y));
        float2 X1 = make_float2(0.5f*(z.y + zc.y), 0.5f*(zc.x - z.x));
        size_t base = (size_t)f*1024 + i0*16 + b;
        g_Xf[base]      = X0;
        g_Xf[base + 16] = X1;
    }
}

// ---------------- per-frequency channel mix (writes Z-packed, coalesced) --------
__global__ __launch_bounds__(256) void mix_kernel(int nMask){
    __shared__ float Xre[1024];
    __shared__ float Xim[1024];
    __shared__ float2 Ws[64 * 65];   // [i][o]; reused as Ysm after GEMM
    int f = blockIdx.x;
    int pr = g_conjRank[f];
    if (pr < f) return;
    int tid = threadIdx.x;
    int uv = g_maskUV[f];
    int u = uv >> 7, v = uv & 127;
    int c = (v <= 30) ? v : v - 67;
    float2 eu1 = g_E[u], eu2 = g_E[(2*u) & 127];
    for (int j = tid; j < 512; j += 256){
        float4 q = g_Xf4[(size_t)f*512 + j];
        int b2 = j*2;
        Xre[b2]   = q.x;  Xim[b2]   = q.y;
        Xre[b2+1] = q.z;  Xim[b2+1] = q.w;
    }
    const float2* Ac = g_A + (size_t)c*3*4096;
    for (int oi = tid; oi < 4096; oi += 256){
        float2 a0 = Ac[oi], a1 = Ac[oi + 4096], a2 = Ac[oi + 8192];
        float2 wv;
        wv.x = a0.x + a1.x*eu1.x - a1.y*eu1.y + a2.x*eu2.x - a2.y*eu2.y;
        wv.y = a0.y + a1.x*eu1.y + a1.y*eu1.x + a2.x*eu2.y + a2.y*eu2.x;
        Ws[(oi & 63)*65 + (oi >> 6)] = wv;
    }
    __syncthreads();
    int o  = tid & 63;
    int bb = (tid >> 6) << 2;
    cplx ax01 = cpack(0.f,0.f), ax23 = ax01, ay01 = ax01, ay23 = ax01;
    #pragma unroll 8
    for (int i = 0; i < 64; i++){
        float2 w = Ws[i*65 + o];
        cplx wx2  = cpack(w.x,  w.x);
        cplx wy2  = cpack(w.y,  w.y);
        cplx wny2 = cpack(-w.y, -w.y);
        float4 r4 = *(const float4*)&Xre[i*16 + bb];
        float4 m4 = *(const float4*)&Xim[i*16 + bb];
        cplx re01 = cpack(r4.x, r4.y), re23 = cpack(r4.z, r4.w);
        cplx im01 = cpack(m4.x, m4.y), im23 = cpack(m4.z, m4.w);
        ax01 = cfma2(re01, wx2,  ax01);  ax01 = cfma2(im01, wny2, ax01);
        ax23 = cfma2(re23, wx2,  ax23);  ax23 = cfma2(im23, wny2, ax23);
        ay01 = cfma2(re01, wy2,  ay01);  ay01 = cfma2(im01, wx2,  ay01);
        ay23 = cfma2(re23, wy2,  ay23);  ay23 = cfma2(im23, wx2,  ay23);
    }
    float2 a0 = make_float2(clo(ax01), clo(ay01));
    float2 a1 = make_float2(chi(ax01), chi(ay01));
    float2 a2 = make_float2(clo(ax23), clo(ay23));
    float2 a3 = make_float2(chi(ax23), chi(ay23));
    // stage Y into smem (reuse Ws), then Z-pack with coalesced writes
    __syncthreads();                 // all GEMM reads of Ws done
    float2* Ysm = Ws;
    Ysm[(bb+0)*64 + o] = a0;
    Ysm[(bb+1)*64 + o] = a1;
    Ysm[(bb+2)*64 + o] = a2;
    Ysm[(bb+3)*64 + o] = a3;
    __syncthreads();
    for (int z = tid; z < 512; z += 256){
        float2 y0 = Ysm[2*z], y1 = Ysm[2*z + 1];   // b*64+2*zo == 2*(b*32+zo)
        g_Yz[(size_t)f*512 + z] = make_float2(y0.x - y1.y, y0.y + y1.x);
        if (pr != f)
            g_Yz[(size_t)pr*512 + z] = make_float2(y0.x + y1.y, y1.x - y0.y);
    }
}

// ---------------- tiled transpose: g_Yz[f][zi] -> g_YzT[zi][f] -------------------
__global__ __launch_bounds__(256) void transpose_kernel(int nMask){
    __shared__ float2 tile[32][33];
    int f0 = blockIdx.x * 32, z0 = blockIdx.y * 32;
    int tx = threadIdx.x & 31, ty = threadIdx.x >> 5;   // 32 x 8
    #pragma unroll
    for (int r = ty; r < 32; r += 8){
        int f = f0 + r;
        if (f < nMask) tile[r][tx] = g_Yz[(size_t)f*512 + z0 + tx];
    }
    __syncthreads();
    #pragma unroll
    for (int r = ty; r < 32; r += 8){
        int f = f0 + tx;
        if (f < nMask) g_YzT[(size_t)(z0 + r)*NF_MAX + f] = tile[tx][r];
    }
}

// ---------------- inverse -------------------------------------------------------
__global__ __launch_bounds__(384, 2) void inv_kernel(float* __restrict__ out,
                                                     const float* __restrict__ bias, int nMask){
    extern __shared__ cplx smemBuf[];
    cplx* ctile = smemBuf;
    cplx* stg   = smemBuf + CTILE_CPLX;
    __shared__ float4 tw4[64];
    int tid = threadIdx.x, lane = tid & 31, wid = tid >> 5;
    if (tid < 64){ float2 e = g_E[tid]; tw4[tid] = make_float4(e.x, -e.y, e.y, e.x); }
    int b = blockIdx.x >> 5, op = blockIdx.x & 31;
    int o0 = 2*op;
    int bsrc = (b + 8) & 15;
    int osrc = (o0 + 32) & 63;
    {
        float4 z4 = make_float4(0.f, 0.f, 0.f, 0.f);
        float4* d4 = (float4*)ctile;
        for (int t = tid; t < CTILE_CPLX/2; t += 384) d4[t] = z4;
    }
    __syncthreads();

    // coalesced read of one contiguous Z row, direct scatter
    float2* ct2 = (float2*)ctile;
    const float2* zrow = g_YzT + (size_t)(bsrc*32 + (osrc >> 1))*NF_MAX;
    for (int f = tid; f < nMask; f += 384)
        ct2[g_offA[f]] = zrow[f];
    __syncthreads();

    for (int t = tid; t < 512; t += 384){
        int c = t & 63, blk = t >> 6;
        dit16_body(ctile, tw4, c*TPC + blk*16, 1);
    }
    __syncthreads();
    for (int t = tid; t < 1024; t += 384){
        int j = t & 15, c = t >> 4;
        dit8_body(ctile, tw4, c*TPC + j, 16, j);
    }
    __syncthreads();

    float bv0 = bias[o0], bv1 = bias[o0 + 1];
    float* d0 = out + (size_t)(b*64 + o0) * 16384;
    float* d1 = d0 + 16384;
    const float sc = 1.f / 16384.f;
    cplx* wst = stg + wid*2*SPITCH;
    cplx zero = cpack(0.f, 0.f);
    for (int pr = wid; pr < 64; pr += 12){
        if (lane < 16){
            int rr = lane >> 3, blk = lane & 7;
            int row = 2*pr + rr;
            int rb = ((blk & 1) << 2) | (blk & 2) | (blk >> 2);
            cplx xv[16];
            #pragma unroll
            for (int m = 0; m < 16; m++){
                int v = V16[m] + rb;
                cplx val = zero;
                if (v <= 30)      val = ctile[v*TPC + row];
                else if (v >= 98) val = ctile[(v - 67)*TPC + row];
                xv[m] = val;
            }
            dit16_core(xv, tw4);
            cplx* dst = wst + rr*SPITCH + blk*17;
            #pragma unroll
            for (int m = 0; m < 16; m++) dst[m] = xv[m];
        }
        __syncwarp();
        {   int rr = lane >> 4, j = lane & 15;
            dit8_body(wst, tw4, rr*SPITCH + j, 17, j); }
        __syncwarp();
        #pragma unroll
        for (int rr = 0; rr < 2; rr++){
            int row = 2*pr + rr;
            const cplx* src = wst + rr*SPITCH + 4*lane + (lane >> 2);
            cplx w0 = src[0], w1 = src[1], w2 = src[2], w3 = src[3];
            ((float4*)(d0 + row*128))[lane] =
                make_float4(clo(w0)*sc + bv0, clo(w1)*sc + bv0, clo(w2)*sc + bv0, clo(w3)*sc + bv0);
            ((float4*)(d1 + row*128))[lane] =
                make_float4(chi(w0)*sc + bv1, chi(w1)*sc + bv1, chi(w2)*sc + bv1, chi(w3)*sc + bv1);
        }
        __syncwarp();
    }
}

// ---------------- launch --------------------------------------------------------
extern "C" void kernel_launch(void* const* d_in, const int* in_sizes, int n_in,
                              void* d_out, int out_size){
    const float* x    = (const float*)d_in[0];
    const float* wgt  = (const float*)d_in[1];
    const float* bias = (const float*)d_in[2];
    float* out = (float*)d_out;

    int nMask = 0;
    for (int u = 0; u < 128; u++){
        int du = (u < 64) ? u : u - 128;
        for (int v = 0; v < 128; v++){
            int dv = (v < 64) ? v : v - 128;
            if (du*du + dv*dv <= 900) nMask++;
        }
    }

    cudaFuncSetAttribute(fwd_kernel, cudaFuncAttributeMaxDynamicSharedMemorySize, (int)SMEM_BYTES);
    cudaFuncSetAttribute(inv_kernel, cudaFuncAttributeMaxDynamicSharedMemorySize, (int)SMEM_BYTES);

    setup_kernel<<<260, 1024>>>(wgt);
    fwd_kernel<<<512, 384, SMEM_BYTES>>>(x, nMask);
    mix_kernel<<<nMask, 256>>>(nMask);
    dim3 tg((nMask + 31) / 32, 16);
    transpose_kernel<<<tg, 256>>>(nMask);
    inv_kernel<<<512, 384, SMEM_BYTES>>>(out, bias, nMask);
}

// round 15
// speedup vs baseline: 1.0424x; 1.0132x over previous
#include <cuda_runtime.h>

#define TPC 129                                     // compact tile pitch (h dim)
#define SPITCH 136                                  // padded staging row pitch (128 + 8)
#define NF_MAX 2850
#define CTILE_CPLX (64 * TPC)                       // 8256 cplx
#define STG_CPLX   (12 * 2 * SPITCH)                // 3264 cplx
#define SMEM_BYTES ((CTILE_CPLX + STG_CPLX) * 8)    // 92160 B

// ---------------- device scratch ------------------------------------------------
__device__ float2 g_E[128];
__device__ int    g_maskUV[NF_MAX];
__device__ int    g_conjRank[NF_MAX];
__device__ int    g_offA[NF_MAX];                   // cidx(v)*TPC + brev7(u)
__device__ int    g_offB[NF_MAX];
__device__ float2 g_A[61 * 3 * 4096];
__device__ float4 g_Xf4[(size_t)NF_MAX * 512];      // [f][i*16+b] /2
__device__ float2 g_Yz [(size_t)NF_MAX * 512];      // [f][b*32+zo]  Z-packed spectrum
#define g_Xf ((float2*)g_Xf4)

typedef unsigned long long cplx;                    // packed (re, im) f32x2

__device__ __forceinline__ int brev7(int x) { return (int)(__brev((unsigned)x) >> 25); }

// ---------------- packed f32x2 complex helpers ----------------------------------
__device__ __forceinline__ cplx cpack(float x, float y){
    cplx r; asm("mov.b64 %0, {%1, %2};" : "=l"(r) : "f"(x), "f"(y)); return r;
}
__device__ __forceinline__ float clo(cplx a){
    float x; asm("{ .reg .f32 hi; mov.b64 {%0, hi}, %1; }" : "=f"(x) : "l"(a)); return x;
}
__device__ __forceinline__ float chi(cplx a){
    float y; asm("{ .reg .f32 lo; mov.b64 {lo, %0}, %1; }" : "=f"(y) : "l"(a)); return y;
}
__device__ __forceinline__ cplx cadd2(cplx a, cplx b){
    cplx r; asm("add.rn.f32x2 %0, %1, %2;" : "=l"(r) : "l"(a), "l"(b)); return r;
}
__device__ __forceinline__ cplx csub2(cplx a, cplx b){
    cplx r; asm("sub.rn.f32x2 %0, %1, %2;" : "=l"(r) : "l"(a), "l"(b)); return r;
}
__device__ __forceinline__ cplx cmul2(cplx a, cplx b){
    cplx r; asm("mul.rn.f32x2 %0, %1, %2;" : "=l"(r) : "l"(a), "l"(b)); return r;
}
__device__ __forceinline__ cplx cfma2(cplx a, cplx b, cplx c){
    cplx r; asm("fma.rn.f32x2 %0, %1, %2, %3;" : "=l"(r) : "l"(a), "l"(b), "l"(c)); return r;
}
__device__ __forceinline__ cplx cmulT(cplx b, float4 t){
    float bx = clo(b), by = chi(b);
    return cfma2(cpack(by, by), cpack(t.z, t.w), cmul2(cpack(bx, bx), cpack(t.x, t.y)));
}
__device__ __forceinline__ cplx cmulnegi(cplx a){
    float x = clo(a), y = chi(a); return cpack(y, -x);
}
__device__ __forceinline__ cplx cmulposi(cplx a){
    float x = clo(a), y = chi(a); return cpack(-y, x);
}

// ---------------- merged setup: prep_A (blocks 0..243) + init (blocks 244..259) --
__device__ __forceinline__ int vmaxOf(int rem){
    int vm = __float2int_rd(sqrtf((float)rem));
    while (vm*vm > rem) vm--;
    while ((vm+1)*(vm+1) <= rem) vm++;
    return vm;
}

__global__ __launch_bounds__(1024) void setup_kernel(const float* __restrict__ wgt){
    int blk = blockIdx.x, tid = threadIdx.x;
    if (blk < 244){
        __shared__ float2 se1, se2;
        int c = blk >> 2;
        if (tid == 0){
            int v = (c <= 30) ? c : c + 67;
            double a1 = -6.283185307179586476925286766559 * (double)v / 128.0;
            double a2 = -6.283185307179586476925286766559 * (double)((2*v) & 127) / 128.0;
            se1 = make_float2((float)cos(a1), (float)sin(a1));
            se2 = make_float2((float)cos(a2), (float)sin(a2));
        }
        __syncthreads();
        float2 e1 = se1, e2 = se2;
        int oi = ((blk & 3) << 10) + tid;
        const float* w9 = wgt + oi*9;
        #pragma unroll
        for (int p = 0; p < 3; p++){
            float w0 = w9[p*3], w1 = w9[p*3+1], w2 = w9[p*3+2];
            float2 acc;
            acc.x = w0 + w1*e1.x + w2*e2.x;
            acc.y =      w1*e1.y + w2*e2.y;
            g_A[((size_t)c*3 + p)*4096 + oi] = acc;
        }
    } else {
        __shared__ int rowBase[128];
        __shared__ int vmax[128];
        int ib = blk - 244;
        if (ib == 0 && tid <= 32){
            double ang = -6.283185307179586476925286766559 * (double)tid / 128.0;
            float c = (float)cos(ang), s = (float)sin(ang);
            if (tid == 0)      { g_E[0]  = make_float2(1.f, 0.f);  g_E[64] = make_float2(-1.f, 0.f); }
            else if (tid == 32){ g_E[32] = make_float2(0.f, -1.f); g_E[96] = make_float2(0.f, 1.f); }
            else {
                g_E[tid]       = make_float2( c,  s);
                g_E[64 - tid]  = make_float2(-c,  s);
                g_E[64 + tid]  = make_float2(-c, -s);
                g_E[128 - tid] = make_float2( c, -s);
            }
        }
        if (tid < 128){
            int du = (tid < 64) ? tid : tid - 128;
            int rem = 900 - du*du;
            vmax[tid] = (rem >= 0) ? vmaxOf(rem) : -1;
        }
        __syncthreads();
        if (tid == 0){
            int s = 0;
            for (int u = 0; u < 128; u++){ rowBase[u] = s; if (vmax[u] >= 0) s += 2*vmax[u] + 1; }
        }
        __syncthreads();
        int t = ib * 1024 + tid;
        if (t < 16384){
            int u = t >> 7, v = t & 127;
            int vm = vmax[u];
            if (vm >= 0){
                int dv = (v < 64) ? v : v - 128;
                if (dv >= -vm && dv <= vm){
                    int r = rowBase[u] + ((v <= vm) ? v : v - (128 - vm) + vm + 1);
                    int uc = (128 - u) & 127, vc = (128 - v) & 127;
                    int vmc = vmax[uc];
                    int rc = rowBase[uc] + ((vc <= vmc) ? vc : vc - (128 - vmc) + vmc + 1);
                    int cA = (v  <= 30) ? v  : v  - 67;
                    int cB = (vc <= 30) ? vc : vc - 67;
                    g_maskUV[r]   = t;
                    g_conjRank[r] = rc;
                    g_offA[r]     = cA*TPC + brev7(u);
                    g_offB[r]     = cB*TPC + brev7(uc);
                }
            }
        }
    }
}

// ---------------- packed radix bodies -------------------------------------------
__device__ __forceinline__ void dif8_body(cplx* d, const float4* t4, int base, int stp, int j){
    cplx x[8];
    #pragma unroll
    for (int m = 0; m < 8; m++) x[m] = d[base + m*stp];
    #pragma unroll
    for (int m = 0; m < 4; m++){
        cplx a = x[m], b = x[m+4];
        x[m] = cadd2(a,b); x[m+4] = cmulT(csub2(a,b), t4[j + 16*m]);
    }
    {
        float4 w0 = t4[2*j], w1 = t4[2*j + 32]; cplx a, b;
        a=x[0]; b=x[2]; x[0]=cadd2(a,b); x[2]=cmulT(csub2(a,b), w0);
        a=x[1]; b=x[3]; x[1]=cadd2(a,b); x[3]=cmulT(csub2(a,b), w1);
        a=x[4]; b=x[6]; x[4]=cadd2(a,b); x[6]=cmulT(csub2(a,b), w0);
        a=x[5]; b=x[7]; x[5]=cadd2(a,b); x[7]=cmulT(csub2(a,b), w1);
    }
    {
        float4 w = t4[4*j];
        #pragma unroll
        for (int m = 0; m < 8; m += 2){
            cplx a = x[m], b = x[m+1];
            x[m] = cadd2(a,b); x[m+1] = cmulT(csub2(a,b), w);
        }
    }
    #pragma unroll
    for (int m = 0; m < 8; m++) d[base + m*stp] = x[m];
}

__device__ __forceinline__ void dif16_core(cplx* x, const float4* t4){
    #pragma unroll
    for (int m = 0; m < 8; m++){
        cplx a = x[m], b = x[m+8];
        x[m] = cadd2(a,b); x[m+8] = cmulT(csub2(a,b), t4[8*m]);
    }
    #pragma unroll
    for (int m = 0; m < 4; m++){
        float4 w = t4[16*m]; cplx a, b;
        a=x[m];   b=x[m+4];  x[m]  =cadd2(a,b); x[m+4] =cmulT(csub2(a,b), w);
        a=x[m+8]; b=x[m+12]; x[m+8]=cadd2(a,b); x[m+12]=cmulT(csub2(a,b), w);
    }
    #pragma unroll
    for (int g = 0; g < 4; g++){
        int b0 = 4*g; cplx a, b;
        a=x[b0];   b=x[b0+2]; x[b0]  =cadd2(a,b); x[b0+2]=csub2(a,b);
        a=x[b0+1]; b=x[b0+3]; x[b0+1]=cadd2(a,b); x[b0+3]=cmulnegi(csub2(a,b));
    }
    #pragma unroll
    for (int m = 0; m < 16; m += 2){
        cplx a = x[m], b = x[m+1];
        x[m] = cadd2(a,b); x[m+1] = csub2(a,b);
    }
}

__device__ __forceinline__ void dif16_body(cplx* d, const float4* t4, int base, int es){
    cplx x[16];
    #pragma unroll
    for (int m = 0; m < 16; m++) x[m] = d[base + m*es];
    dif16_core(x, t4);
    #pragma unroll
    for (int m = 0; m < 16; m++) d[base + m*es] = x[m];
}

__device__ __forceinline__ void dit16_core(cplx* x, const float4* t4){
    #pragma unroll
    for (int m = 0; m < 16; m += 2){
        cplx a = x[m], b = x[m+1];
        x[m] = cadd2(a,b); x[m+1] = csub2(a,b);
    }
    #pragma unroll
    for (int g = 0; g < 4; g++){
        int b0 = 4*g; cplx a, tt;
        a=x[b0];   tt=x[b0+2];           x[b0]  =cadd2(a,tt); x[b0+2]=csub2(a,tt);
        a=x[b0+1]; tt=cmulposi(x[b0+3]); x[b0+1]=cadd2(a,tt); x[b0+3]=csub2(a,tt);
    }
    #pragma unroll
    for (int m = 0; m < 4; m++){
        float4 w = t4[16*m]; cplx a, tt;
        a=x[m];   tt=cmulT(x[m+4],  w); x[m]  =cadd2(a,tt); x[m+4] =csub2(a,tt);
        a=x[m+8]; tt=cmulT(x[m+12], w); x[m+8]=cadd2(a,tt); x[m+12]=csub2(a,tt);
    }
    #pragma unroll
    for (int m = 0; m < 8; m++){
        cplx a = x[m], tt = cmulT(x[m+8], t4[8*m]);
        x[m] = cadd2(a,tt); x[m+8] = csub2(a,tt);
    }
}

__device__ __forceinline__ void dit16_body(cplx* d, const float4* t4, int base, int es){
    cplx x[16];
    #pragma unroll
    for (int m = 0; m < 16; m++) x[m] = d[base + m*es];
    dit16_core(x, t4);
    #pragma unroll
    for (int m = 0; m < 16; m++) d[base + m*es] = x[m];
}

__device__ __forceinline__ void dit8_body(cplx* d, const float4* t4, int base, int stp, int j){
    cplx x[8];
    #pragma unroll
    for (int m = 0; m < 8; m++) x[m] = d[base + m*stp];
    {
        float4 w = t4[4*j];
        #pragma unroll
        for (int m = 0; m < 8; m += 2){
            cplx a = x[m], tt = cmulT(x[m+1], w);
            x[m] = cadd2(a,tt); x[m+1] = csub2(a,tt);
        }
    }
    {
        float4 w0 = t4[2*j], w1 = t4[2*j + 32]; cplx a, tt;
        a=x[0]; tt=cmulT(x[2], w0); x[0]=cadd2(a,tt); x[2]=csub2(a,tt);
        a=x[1]; tt=cmulT(x[3], w1); x[1]=cadd2(a,tt); x[3]=csub2(a,tt);
        a=x[4]; tt=cmulT(x[6], w0); x[4]=cadd2(a,tt); x[6]=csub2(a,tt);
        a=x[5]; tt=cmulT(x[7], w1); x[5]=cadd2(a,tt); x[7]=csub2(a,tt);
    }
    #pragma unroll
    for (int m = 0; m < 4; m++){
        cplx a = x[m], tt = cmulT(x[m+4], t4[j + 16*m]);
        x[m] = cadd2(a,tt); x[m+4] = csub2(a,tt);
    }
    #pragma unroll
    for (int m = 0; m < 8; m++) d[base + m*stp] = x[m];
}

__device__ __constant__ int V16[16] = {0,64,32,96,16,80,48,112,8,72,40,104,24,88,56,120};

// ---------------- forward -------------------------------------------------------
__global__ __launch_bounds__(384, 2) void fwd_kernel(const float* __restrict__ x, int nMask){
    extern __shared__ cplx smemBuf[];
    cplx* ctile = smemBuf;
    cplx* stg   = smemBuf + CTILE_CPLX;
    __shared__ float4 tw4[64];
    int tid = threadIdx.x, lane = tid & 31, wid = tid >> 5;
    if (tid < 64){ float2 e = g_E[tid]; tw4[tid] = make_float4(e.x, e.y, -e.y, e.x); }
    int b = blockIdx.x >> 5, ip = blockIdx.x & 31;
    int i0 = 2*ip;
    const float* s0 = x + (size_t)(b*64 + i0) * 16384;
    const float* s1 = s0 + 16384;
    __syncthreads();

    cplx* wst = stg + wid*2*SPITCH;
    for (int pr = wid; pr < 64; pr += 12){
        #pragma unroll
        for (int rr = 0; rr < 2; rr++){
            int row = 2*pr + rr;
            float4 a = ((const float4*)(s0 + row*128))[lane];
            float4 c = ((const float4*)(s1 + row*128))[lane];
            cplx* dst = wst + rr*SPITCH + 4*lane + (lane >> 2);
            dst[0] = cpack(a.x, c.x);
            dst[1] = cpack(a.y, c.y);
            dst[2] = cpack(a.z, c.z);
            dst[3] = cpack(a.w, c.w);
        }
        __syncwarp();
        {   int rr = lane >> 4, j = lane & 15;
            dif8_body(wst, tw4, rr*SPITCH + j, 17, j); }
        __syncwarp();
        if (lane < 16){
            int rr = lane >> 3, blk = lane & 7;
            int row = 2*pr + rr;
            int rb = ((blk & 1) << 2) | (blk & 2) | (blk >> 2);
            cplx xv[16];
            cplx* src = wst + rr*SPITCH + blk*17;
            #pragma unroll
            for (int m = 0; m < 16; m++) xv[m] = src[m];
            dif16_core(xv, tw4);
            #pragma unroll
            for (int m = 0; m < 16; m++){
                int v = V16[m] + rb;
                if (v <= 30)       ctile[v*TPC + row]        = xv[m];
                else if (v >= 98)  ctile[(v - 67)*TPC + row] = xv[m];
            }
        }
        __syncwarp();
    }
    __syncthreads();

    for (int t = tid; t < 1024; t += 384){
        int j = t & 15, c = t >> 4;
        dif8_body(ctile, tw4, c*TPC + j, 16, j);
    }
    __syncthreads();
    for (int t = tid; t < 512; t += 384){
        int c = t & 63, blk = t >> 6;
        dif16_body(ctile, tw4, c*TPC + blk*16, 1);
    }
    __syncthreads();

    float2* ct2 = (float2*)ctile;
    for (int f = tid; f < nMask; f += 384){
        int pr = g_conjRank[f];
        if (pr < f) continue;
        float2 z  = ct2[g_offA[f]];
        float2 zc = ct2[g_offB[f]];
        float2 X0 = make_float2(0.5f*(z.x + zc.x), 0.5f*(z.y - zc.y));
        float2 X1 = make_float2(0.5f*(z.y + zc.y), 0.5f*(zc.x - z.x));
        size_t base = (size_t)f*1024 + i0*16 + b;
        g_Xf[base]      = X0;
        g_Xf[base + 16] = X1;
    }
}

// ---------------- per-frequency channel mix (writes Z-packed, coalesced) --------
__global__ __launch_bounds__(256) void mix_kernel(int nMask){
    __shared__ float Xre[1024];
    __shared__ float Xim[1024];
    __shared__ float2 Ws[64 * 65];   // [i][o]; reused as Ysm after GEMM
    int f = blockIdx.x;
    int pr = g_conjRank[f];
    if (pr < f) return;
    int tid = threadIdx.x;
    int uv = g_maskUV[f];
    int u = uv >> 7, v = uv & 127;
    int c = (v <= 30) ? v : v - 67;
    float2 eu1 = g_E[u], eu2 = g_E[(2*u) & 127];
    for (int j = tid; j < 512; j += 256){
        float4 q = g_Xf4[(size_t)f*512 + j];
        int b2 = j*2;
        Xre[b2]   = q.x;  Xim[b2]   = q.y;
        Xre[b2+1] = q.z;  Xim[b2+1] = q.w;
    }
    const float2* Ac = g_A + (size_t)c*3*4096;
    for (int oi = tid; oi < 4096; oi += 256){
        float2 a0 = Ac[oi], a1 = Ac[oi + 4096], a2 = Ac[oi + 8192];
        float2 wv;
        wv.x = a0.x + a1.x*eu1.x - a1.y*eu1.y + a2.x*eu2.x - a2.y*eu2.y;
        wv.y = a0.y + a1.x*eu1.y + a1.y*eu1.x + a2.x*eu2.y + a2.y*eu2.x;
        Ws[(oi & 63)*65 + (oi >> 6)] = wv;
    }
    __syncthreads();
    int o  = tid & 63;
    int bb = (tid >> 6) << 2;
    cplx ax01 = cpack(0.f,0.f), ax23 = ax01, ay01 = ax01, ay23 = ax01;
    #pragma unroll 8
    for (int i = 0; i < 64; i++){
        float2 w = Ws[i*65 + o];
        cplx wx2  = cpack(w.x,  w.x);
        cplx wy2  = cpack(w.y,  w.y);
        cplx wny2 = cpack(-w.y, -w.y);
        float4 r4 = *(const float4*)&Xre[i*16 + bb];
        float4 m4 = *(const float4*)&Xim[i*16 + bb];
        cplx re01 = cpack(r4.x, r4.y), re23 = cpack(r4.z, r4.w);
        cplx im01 = cpack(m4.x, m4.y), im23 = cpack(m4.z, m4.w);
        ax01 = cfma2(re01, wx2,  ax01);  ax01 = cfma2(im01, wny2, ax01);
        ax23 = cfma2(re23, wx2,  ax23);  ax23 = cfma2(im23, wny2, ax23);
        ay01 = cfma2(re01, wy2,  ay01);  ay01 = cfma2(im01, wx2,  ay01);
        ay23 = cfma2(re23, wy2,  ay23);  ay23 = cfma2(im23, wx2,  ay23);
    }
    float2 a0 = make_float2(clo(ax01), clo(ay01));
    float2 a1 = make_float2(chi(ax01), chi(ay01));
    float2 a2 = make_float2(clo(ax23), clo(ay23));
    float2 a3 = make_float2(chi(ax23), chi(ay23));
    // stage Y into smem (reuse Ws), then Z-pack with coalesced writes
    __syncthreads();                 // all GEMM reads of Ws done
    float2* Ysm = Ws;
    Ysm[(bb+0)*64 + o] = a0;
    Ysm[(bb+1)*64 + o] = a1;
    Ysm[(bb+2)*64 + o] = a2;
    Ysm[(bb+3)*64 + o] = a3;
    __syncthreads();
    for (int z = tid; z < 512; z += 256){
        float2 y0 = Ysm[2*z], y1 = Ysm[2*z + 1];   // b*64+2*zo == 2*(b*32+zo)
        g_Yz[(size_t)f*512 + z] = make_float2(y0.x - y1.y, y0.y + y1.x);
        if (pr != f)
            g_Yz[(size_t)pr*512 + z] = make_float2(y0.x + y1.y, y1.x - y0.y);
    }
}

// ---------------- inverse -------------------------------------------------------
__global__ __launch_bounds__(384, 2) void inv_kernel(float* __restrict__ out,
                                                     const float* __restrict__ bias, int nMask){
    extern __shared__ cplx smemBuf[];
    cplx* ctile = smemBuf;
    cplx* stg   = smemBuf + CTILE_CPLX;
    __shared__ float4 tw4[64];
    int tid = threadIdx.x, lane = tid & 31, wid = tid >> 5;
    if (tid < 64){ float2 e = g_E[tid]; tw4[tid] = make_float4(e.x, -e.y, e.y, e.x); }
    int b = blockIdx.x >> 5, op = blockIdx.x & 31;
    int o0 = 2*op;
    int bsrc = (b + 8) & 15;
    int osrc = (o0 + 32) & 63;
    {
        float4 z4 = make_float4(0.f, 0.f, 0.f, 0.f);
        float4* d4 = (float4*)ctile;
        for (int t = tid; t < CTILE_CPLX/2; t += 384) d4[t] = z4;
    }
    __syncthreads();

    // scattered reads of Z column (one float2 per f), batched 4-wide for MLP
    float2* ct2 = (float2*)ctile;
    const float2* zcol = g_Yz + (bsrc*32 + (osrc >> 1));
    int f = tid;
    for (; f + 1152 < nMask; f += 1536){
        float2 z0 = __ldg(&zcol[(size_t)(f       )*512]);
        float2 z1 = __ldg(&zcol[(size_t)(f +  384)*512]);
        float2 z2 = __ldg(&zcol[(size_t)(f +  768)*512]);
        float2 z3 = __ldg(&zcol[(size_t)(f + 1152)*512]);
        int o0i = g_offA[f], o1i = g_offA[f + 384];
        int o2i = g_offA[f + 768], o3i = g_offA[f + 1152];
        ct2[o0i] = z0; ct2[o1i] = z1; ct2[o2i] = z2; ct2[o3i] = z3;
    }
    for (; f < nMask; f += 384)
        ct2[g_offA[f]] = __ldg(&zcol[(size_t)f*512]);
    __syncthreads();

    for (int t = tid; t < 512; t += 384){
        int c = t & 63, blk = t >> 6;
        dit16_body(ctile, tw4, c*TPC + blk*16, 1);
    }
    __syncthreads();
    for (int t = tid; t < 1024; t += 384){
        int j = t & 15, c = t >> 4;
        dit8_body(ctile, tw4, c*TPC + j, 16, j);
    }
    __syncthreads();

    float bv0 = bias[o0], bv1 = bias[o0 + 1];
    float* d0 = out + (size_t)(b*64 + o0) * 16384;
    float* d1 = d0 + 16384;
    const float sc = 1.f / 16384.f;
    cplx* wst = stg + wid*2*SPITCH;
    cplx zero = cpack(0.f, 0.f);
    for (int pr = wid; pr < 64; pr += 12){
        if (lane < 16){
            int rr = lane >> 3, blk = lane & 7;
            int row = 2*pr + rr;
            int rb = ((blk & 1) << 2) | (blk & 2) | (blk >> 2);
            cplx xv[16];
            #pragma unroll
            for (int m = 0; m < 16; m++){
                int v = V16[m] + rb;
                cplx val = zero;
                if (v <= 30)      val = ctile[v*TPC + row];
                else if (v >= 98) val = ctile[(v - 67)*TPC + row];
                xv[m] = val;
            }
            dit16_core(xv, tw4);
            cplx* dst = wst + rr*SPITCH + blk*17;
            #pragma unroll
            for (int m = 0; m < 16; m++) dst[m] = xv[m];
        }
        __syncwarp();
        {   int rr = lane >> 4, j = lane & 15;
            dit8_body(wst, tw4, rr*SPITCH + j, 17, j); }
        __syncwarp();
        #pragma unroll
        for (int rr = 0; rr < 2; rr++){
            int row = 2*pr + rr;
            const cplx* src = wst + rr*SPITCH + 4*lane + (lane >> 2);
            cplx w0 = src[0], w1 = src[1], w2 = src[2], w3 = src[3];
            ((float4*)(d0 + row*128))[lane] =
                make_float4(clo(w0)*sc + bv0, clo(w1)*sc + bv0, clo(w2)*sc + bv0, clo(w3)*sc + bv0);
            ((float4*)(d1 + row*128))[lane] =
                make_float4(chi(w0)*sc + bv1, chi(w1)*sc + bv1, chi(w2)*sc + bv1, chi(w3)*sc + bv1);
        }
        __syncwarp();
    }
}

// ---------------- launch --------------------------------------------------------
extern "C" void kernel_launch(void* const* d_in, const int* in_sizes, int n_in,
                              void* d_out, int out_size){
    const float* x    = (const float*)d_in[0];
    const float* wgt  = (const float*)d_in[1];
    const float* bias = (const float*)d_in[2];
    float* out = (float*)d_out;

    int nMask = 0;
    for (int u = 0; u < 128; u++){
        int du = (u < 64) ? u : u - 128;
        for (int v = 0; v < 128; v++){
            int dv = (v < 64) ? v : v - 128;
            if (du*du + dv*dv <= 900) nMask++;
        }
    }

    cudaFuncSetAttribute(fwd_kernel, cudaFuncAttributeMaxDynamicSharedMemorySize, (int)SMEM_BYTES);
    cudaFuncSetAttribute(inv_kernel, cudaFuncAttributeMaxDynamicSharedMemorySize, (int)SMEM_BYTES);

    setup_kernel<<<260, 1024>>>(wgt);
    fwd_kernel<<<512, 384, SMEM_BYTES>>>(x, nMask);
    mix_kernel<<<nMask, 256>>>(nMask);
    inv_kernel<<<512, 384, SMEM_BYTES>>>(out, bias, nMask);
}

// round 16
// speedup vs baseline: 1.0461x; 1.0036x over previous
#include <cuda_runtime.h>

#define TPC 129                                     // compact tile pitch (h dim)
#define SPITCH 136                                  // padded staging row pitch (128 + 8)
#define NF_MAX 2850
#define CTILE_CPLX (64 * TPC)                       // 8256 cplx
#define STG_CPLX   (12 * 2 * SPITCH)                // 3264 cplx
#define SMEM_BYTES ((CTILE_CPLX + STG_CPLX) * 8)    // 92160 B

// ---------------- device scratch ------------------------------------------------
__device__ float2 g_E[128];
__device__ int    g_maskUV[NF_MAX];
__device__ int    g_conjRank[NF_MAX];
__device__ int    g_offA[NF_MAX];                   // cidx(v)*TPC + brev7(u)
__device__ int    g_offB[NF_MAX];
__device__ int    g_rowOf[NF_MAX];                  // primary compact index, or -1
__device__ int    g_pOffA[NF_MAX];                  // per-primary tile offsets
__device__ int    g_pOffB[NF_MAX];
__device__ float2 g_A[61 * 3 * 4096];
__device__ float4 g_Xf4[(size_t)NF_MAX * 512];      // [f][i*16+b] /2
__device__ float4 g_Yp4[(size_t)NF_MAX * 512];      // [j_primary][b*32+zo] = (y0, y1)
#define g_Xf ((float2*)g_Xf4)

typedef unsigned long long cplx;                    // packed (re, im) f32x2

__device__ __forceinline__ int brev7(int x) { return (int)(__brev((unsigned)x) >> 25); }

// ---------------- packed f32x2 complex helpers ----------------------------------
__device__ __forceinline__ cplx cpack(float x, float y){
    cplx r; asm("mov.b64 %0, {%1, %2};" : "=l"(r) : "f"(x), "f"(y)); return r;
}
__device__ __forceinline__ float clo(cplx a){
    float x; asm("{ .reg .f32 hi; mov.b64 {%0, hi}, %1; }" : "=f"(x) : "l"(a)); return x;
}
__device__ __forceinline__ float chi(cplx a){
    float y; asm("{ .reg .f32 lo; mov.b64 {lo, %0}, %1; }" : "=f"(y) : "l"(a)); return y;
}
__device__ __forceinline__ cplx cadd2(cplx a, cplx b){
    cplx r; asm("add.rn.f32x2 %0, %1, %2;" : "=l"(r) : "l"(a), "l"(b)); return r;
}
__device__ __forceinline__ cplx csub2(cplx a, cplx b){
    cplx r; asm("sub.rn.f32x2 %0, %1, %2;" : "=l"(r) : "l"(a), "l"(b)); return r;
}
__device__ __forceinline__ cplx cmul2(cplx a, cplx b){
    cplx r; asm("mul.rn.f32x2 %0, %1, %2;" : "=l"(r) : "l"(a), "l"(b)); return r;
}
__device__ __forceinline__ cplx cfma2(cplx a, cplx b, cplx c){
    cplx r; asm("fma.rn.f32x2 %0, %1, %2, %3;" : "=l"(r) : "l"(a), "l"(b), "l"(c)); return r;
}
__device__ __forceinline__ cplx cmulT(cplx b, float4 t){
    float bx = clo(b), by = chi(b);
    return cfma2(cpack(by, by), cpack(t.z, t.w), cmul2(cpack(bx, bx), cpack(t.x, t.y)));
}
__device__ __forceinline__ cplx cmulnegi(cplx a){
    float x = clo(a), y = chi(a); return cpack(y, -x);
}
__device__ __forceinline__ cplx cmulposi(cplx a){
    float x = clo(a), y = chi(a); return cpack(-y, x);
}

// ---------------- merged setup: prep_A (blocks 0..243) + init (blocks 244..259) --
__device__ __forceinline__ int vmaxOf(int rem){
    int vm = __float2int_rd(sqrtf((float)rem));
    while (vm*vm > rem) vm--;
    while ((vm+1)*(vm+1) <= rem) vm++;
    return vm;
}

__global__ __launch_bounds__(1024) void setup_kernel(const float* __restrict__ wgt){
    int blk = blockIdx.x, tid = threadIdx.x;
    if (blk < 244){
        __shared__ float2 se1, se2;
        int c = blk >> 2;
        if (tid == 0){
            int v = (c <= 30) ? c : c + 67;
            double a1 = -6.283185307179586476925286766559 * (double)v / 128.0;
            double a2 = -6.283185307179586476925286766559 * (double)((2*v) & 127) / 128.0;
            se1 = make_float2((float)cos(a1), (float)sin(a1));
            se2 = make_float2((float)cos(a2), (float)sin(a2));
        }
        __syncthreads();
        float2 e1 = se1, e2 = se2;
        int oi = ((blk & 3) << 10) + tid;
        const float* w9 = wgt + oi*9;
        #pragma unroll
        for (int p = 0; p < 3; p++){
            float w0 = w9[p*3], w1 = w9[p*3+1], w2 = w9[p*3+2];
            float2 acc;
            acc.x = w0 + w1*e1.x + w2*e2.x;
            acc.y =      w1*e1.y + w2*e2.y;
            g_A[((size_t)c*3 + p)*4096 + oi] = acc;
        }
    } else {
        __shared__ int rowBase[128];
        __shared__ int vmax[128];
        __shared__ int primBase[32];
        int ib = blk - 244;
        if (ib == 0 && tid <= 32){
            double ang = -6.283185307179586476925286766559 * (double)tid / 128.0;
            float c = (float)cos(ang), s = (float)sin(ang);
            if (tid == 0)      { g_E[0]  = make_float2(1.f, 0.f);  g_E[64] = make_float2(-1.f, 0.f); }
            else if (tid == 32){ g_E[32] = make_float2(0.f, -1.f); g_E[96] = make_float2(0.f, 1.f); }
            else {
                g_E[tid]       = make_float2( c,  s);
                g_E[64 - tid]  = make_float2(-c,  s);
                g_E[64 + tid]  = make_float2(-c, -s);
                g_E[128 - tid] = make_float2( c, -s);
            }
        }
        if (tid < 128){
            int du = (tid < 64) ? tid : tid - 128;
            int rem = 900 - du*du;
            vmax[tid] = (rem >= 0) ? vmaxOf(rem) : -1;
        }
        __syncthreads();
        if (tid == 0){
            int s = 0;
            for (int u = 0; u < 128; u++){ rowBase[u] = s; if (vmax[u] >= 0) s += 2*vmax[u] + 1; }
            int pj = 31;                          // u=0 contributes primaries j = v for v in [0,30]
            for (int u = 1; u <= 30; u++){ primBase[u] = pj; pj += 2*vmax[u] + 1; }
            primBase[0] = 0;
        }
        __syncthreads();
        int t = ib * 1024 + tid;
        if (t < 16384){
            int u = t >> 7, v = t & 127;
            int vm = vmax[u];
            if (vm >= 0){
                int dv = (v < 64) ? v : v - 128;
                if (dv >= -vm && dv <= vm){
                    int vr = (v <= vm) ? v : v - (128 - vm) + vm + 1;
                    int r = rowBase[u] + vr;
                    int uc = (128 - u) & 127, vc = (128 - v) & 127;
                    int vmc = vmax[uc];
                    int rc = rowBase[uc] + ((vc <= vmc) ? vc : vc - (128 - vmc) + vmc + 1);
                    int cA = (v  <= 30) ? v  : v  - 67;
                    int cB = (vc <= 30) ? vc : vc - 67;
                    int oA = cA*TPC + brev7(u);
                    int oB = cB*TPC + brev7(uc);
                    g_maskUV[r]   = t;
                    g_conjRank[r] = rc;
                    g_offA[r]     = oA;
                    g_offB[r]     = oB;
                    // primary iff u in [1,30], or u==0 && v<=30
                    bool isPrim = (u >= 1 && u <= 30) || (u == 0 && v <= 30);
                    if (isPrim){
                        int j = (u == 0) ? v : (primBase[u] + vr);
                        g_rowOf[r]  = j;
                        g_pOffA[j]  = oA;
                        g_pOffB[j]  = oB;
                    } else {
                        g_rowOf[r] = -1;
                    }
                }
            }
        }
    }
}

// ---------------- packed radix bodies -------------------------------------------
__device__ __forceinline__ void dif8_body(cplx* d, const float4* t4, int base, int stp, int j){
    cplx x[8];
    #pragma unroll
    for (int m = 0; m < 8; m++) x[m] = d[base + m*stp];
    #pragma unroll
    for (int m = 0; m < 4; m++){
        cplx a = x[m], b = x[m+4];
        x[m] = cadd2(a,b); x[m+4] = cmulT(csub2(a,b), t4[j + 16*m]);
    }
    {
        float4 w0 = t4[2*j], w1 = t4[2*j + 32]; cplx a, b;
        a=x[0]; b=x[2]; x[0]=cadd2(a,b); x[2]=cmulT(csub2(a,b), w0);
        a=x[1]; b=x[3]; x[1]=cadd2(a,b); x[3]=cmulT(csub2(a,b), w1);
        a=x[4]; b=x[6]; x[4]=cadd2(a,b); x[6]=cmulT(csub2(a,b), w0);
        a=x[5]; b=x[7]; x[5]=cadd2(a,b); x[7]=cmulT(csub2(a,b), w1);
    }
    {
        float4 w = t4[4*j];
        #pragma unroll
        for (int m = 0; m < 8; m += 2){
            cplx a = x[m], b = x[m+1];
            x[m] = cadd2(a,b); x[m+1] = cmulT(csub2(a,b), w);
        }
    }
    #pragma unroll
    for (int m = 0; m < 8; m++) d[base + m*stp] = x[m];
}

__device__ __forceinline__ void dif16_core(cplx* x, const float4* t4){
    #pragma unroll
    for (int m = 0; m < 8; m++){
        cplx a = x[m], b = x[m+8];
        x[m] = cadd2(a,b); x[m+8] = cmulT(csub2(a,b), t4[8*m]);
    }
    #pragma unroll
    for (int m = 0; m < 4; m++){
        float4 w = t4[16*m]; cplx a, b;
        a=x[m];   b=x[m+4];  x[m]  =cadd2(a,b); x[m+4] =cmulT(csub2(a,b), w);
        a=x[m+8]; b=x[m+12]; x[m+8]=cadd2(a,b); x[m+12]=cmulT(csub2(a,b), w);
    }
    #pragma unroll
    for (int g = 0; g < 4; g++){
        int b0 = 4*g; cplx a, b;
        a=x[b0];   b=x[b0+2]; x[b0]  =cadd2(a,b); x[b0+2]=csub2(a,b);
        a=x[b0+1]; b=x[b0+3]; x[b0+1]=cadd2(a,b); x[b0+3]=cmulnegi(csub2(a,b));
    }
    #pragma unroll
    for (int m = 0; m < 16; m += 2){
        cplx a = x[m], b = x[m+1];
        x[m] = cadd2(a,b); x[m+1] = csub2(a,b);
    }
}

__device__ __forceinline__ void dif16_body(cplx* d, const float4* t4, int base, int es){
    cplx x[16];
    #pragma unroll
    for (int m = 0; m < 16; m++) x[m] = d[base + m*es];
    dif16_core(x, t4);
    #pragma unroll
    for (int m = 0; m < 16; m++) d[base + m*es] = x[m];
}

__device__ __forceinline__ void dit16_core(cplx* x, const float4* t4){
    #pragma unroll
    for (int m = 0; m < 16; m += 2){
        cplx a = x[m], b = x[m+1];
        x[m] = cadd2(a,b); x[m+1] = csub2(a,b);
    }
    #pragma unroll
    for (int g = 0; g < 4; g++){
        int b0 = 4*g; cplx a, tt;
        a=x[b0];   tt=x[b0+2];           x[b0]  =cadd2(a,tt); x[b0+2]=csub2(a,tt);
        a=x[b0+1]; tt=cmulposi(x[b0+3]); x[b0+1]=cadd2(a,tt); x[b0+3]=csub2(a,tt);
    }
    #pragma unroll
    for (int m = 0; m < 4; m++){
        float4 w = t4[16*m]; cplx a, tt;
        a=x[m];   tt=cmulT(x[m+4],  w); x[m]  =cadd2(a,tt); x[m+4] =csub2(a,tt);
        a=x[m+8]; tt=cmulT(x[m+12], w); x[m+8]=cadd2(a,tt); x[m+12]=csub2(a,tt);
    }
    #pragma unroll
    for (int m = 0; m < 8; m++){
        cplx a = x[m], tt = cmulT(x[m+8], t4[8*m]);
        x[m] = cadd2(a,tt); x[m+8] = csub2(a,tt);
    }
}

__device__ __forceinline__ void dit16_body(cplx* d, const float4* t4, int base, int es){
    cplx x[16];
    #pragma unroll
    for (int m = 0; m < 16; m++) x[m] = d[base + m*es];
    dit16_core(x, t4);
    #pragma unroll
    for (int m = 0; m < 16; m++) d[base + m*es] = x[m];
}

__device__ __forceinline__ void dit8_body(cplx* d, const float4* t4, int base, int stp, int j){
    cplx x[8];
    #pragma unroll
    for (int m = 0; m < 8; m++) x[m] = d[base + m*stp];
    {
        float4 w = t4[4*j];
        #pragma unroll
        for (int m = 0; m < 8; m += 2){
            cplx a = x[m], tt = cmulT(x[m+1], w);
            x[m] = cadd2(a,tt); x[m+1] = csub2(a,tt);
        }
    }
    {
        float4 w0 = t4[2*j], w1 = t4[2*j + 32]; cplx a, tt;
        a=x[0]; tt=cmulT(x[2], w0); x[0]=cadd2(a,tt); x[2]=csub2(a,tt);
        a=x[1]; tt=cmulT(x[3], w1); x[1]=cadd2(a,tt); x[3]=csub2(a,tt);
        a=x[4]; tt=cmulT(x[6], w0); x[4]=cadd2(a,tt); x[6]=csub2(a,tt);
        a=x[5]; tt=cmulT(x[7], w1); x[5]=cadd2(a,tt); x[7]=csub2(a,tt);
    }
    #pragma unroll
    for (int m = 0; m < 4; m++){
        cplx a = x[m], tt = cmulT(x[m+4], t4[j + 16*m]);
        x[m] = cadd2(a,tt); x[m+4] = csub2(a,tt);
    }
    #pragma unroll
    for (int m = 0; m < 8; m++) d[base + m*stp] = x[m];
}

__device__ __constant__ int V16[16] = {0,64,32,96,16,80,48,112,8,72,40,104,24,88,56,120};

// ---------------- forward -------------------------------------------------------
__global__ __launch_bounds__(384, 2) void fwd_kernel(const float* __restrict__ x, int nMask){
    extern __shared__ cplx smemBuf[];
    cplx* ctile = smemBuf;
    cplx* stg   = smemBuf + CTILE_CPLX;
    __shared__ float4 tw4[64];
    int tid = threadIdx.x, lane = tid & 31, wid = tid >> 5;
    if (tid < 64){ float2 e = g_E[tid]; tw4[tid] = make_float4(e.x, e.y, -e.y, e.x); }
    int b = blockIdx.x >> 5, ip = blockIdx.x & 31;
    int i0 = 2*ip;
    const float* s0 = x + (size_t)(b*64 + i0) * 16384;
    const float* s1 = s0 + 16384;
    __syncthreads();

    cplx* wst = stg + wid*2*SPITCH;
    for (int pr = wid; pr < 64; pr += 12){
        #pragma unroll
        for (int rr = 0; rr < 2; rr++){
            int row = 2*pr + rr;
            float4 a = ((const float4*)(s0 + row*128))[lane];
            float4 c = ((const float4*)(s1 + row*128))[lane];
            cplx* dst = wst + rr*SPITCH + 4*lane + (lane >> 2);
            dst[0] = cpack(a.x, c.x);
            dst[1] = cpack(a.y, c.y);
            dst[2] = cpack(a.z, c.z);
            dst[3] = cpack(a.w, c.w);
        }
        __syncwarp();
        {   int rr = lane >> 4, j = lane & 15;
            dif8_body(wst, tw4, rr*SPITCH + j, 17, j); }
        __syncwarp();
        if (lane < 16){
            int rr = lane >> 3, blk = lane & 7;
            int row = 2*pr + rr;
            int rb = ((blk & 1) << 2) | (blk & 2) | (blk >> 2);
            cplx xv[16];
            cplx* src = wst + rr*SPITCH + blk*17;
            #pragma unroll
            for (int m = 0; m < 16; m++) xv[m] = src[m];
            dif16_core(xv, tw4);
            #pragma unroll
            for (int m = 0; m < 16; m++){
                int v = V16[m] + rb;
                if (v <= 30)       ctile[v*TPC + row]        = xv[m];
                else if (v >= 98)  ctile[(v - 67)*TPC + row] = xv[m];
            }
        }
        __syncwarp();
    }
    __syncthreads();

    for (int t = tid; t < 1024; t += 384){
        int j = t & 15, c = t >> 4;
        dif8_body(ctile, tw4, c*TPC + j, 16, j);
    }
    __syncthreads();
    for (int t = tid; t < 512; t += 384){
        int c = t & 63, blk = t >> 6;
        dif16_body(ctile, tw4, c*TPC + blk*16, 1);
    }
    __syncthreads();

    float2* ct2 = (float2*)ctile;
    for (int f = tid; f < nMask; f += 384){
        if (g_rowOf[f] < 0) continue;
        float2 z  = ct2[g_offA[f]];
        float2 zc = ct2[g_offB[f]];
        float2 X0 = make_float2(0.5f*(z.x + zc.x), 0.5f*(z.y - zc.y));
        float2 X1 = make_float2(0.5f*(z.y + zc.y), 0.5f*(zc.x - z.x));
        size_t base = (size_t)f*1024 + i0*16 + b;
        g_Xf[base]      = X0;
        g_Xf[base + 16] = X1;
    }
}

// ---------------- per-frequency channel mix (primary blocks only) ---------------
__global__ __launch_bounds__(256) void mix_kernel(int nMask){
    __shared__ float Xre[1024];
    __shared__ float Xim[1024];
    __shared__ float2 Ws[64 * 65];   // [i][o]; reused as Ysm after GEMM
    int f = blockIdx.x;
    int jrow = g_rowOf[f];
    if (jrow < 0) return;
    int tid = threadIdx.x;
    int uv = g_maskUV[f];
    int u = uv >> 7, v = uv & 127;
    int c = (v <= 30) ? v : v - 67;
    float2 eu1 = g_E[u], eu2 = g_E[(2*u) & 127];
    for (int j = tid; j < 512; j += 256){
        float4 q = g_Xf4[(size_t)f*512 + j];
        int b2 = j*2;
        Xre[b2]   = q.x;  Xim[b2]   = q.y;
        Xre[b2+1] = q.z;  Xim[b2+1] = q.w;
    }
    const float2* Ac = g_A + (size_t)c*3*4096;
    for (int oi = tid; oi < 4096; oi += 256){
        float2 a0 = Ac[oi], a1 = Ac[oi + 4096], a2 = Ac[oi + 8192];
        float2 wv;
        wv.x = a0.x + a1.x*eu1.x - a1.y*eu1.y + a2.x*eu2.x - a2.y*eu2.y;
        wv.y = a0.y + a1.x*eu1.y + a1.y*eu1.x + a2.x*eu2.y + a2.y*eu2.x;
        Ws[(oi & 63)*65 + (oi >> 6)] = wv;
    }
    __syncthreads();
    int o  = tid & 63;
    int bb = (tid >> 6) << 2;
    cplx ax01 = cpack(0.f,0.f), ax23 = ax01, ay01 = ax01, ay23 = ax01;
    #pragma unroll 8
    for (int i = 0; i < 64; i++){
        float2 w = Ws[i*65 + o];
        cplx wx2  = cpack(w.x,  w.x);
        cplx wy2  = cpack(w.y,  w.y);
        cplx wny2 = cpack(-w.y, -w.y);
        float4 r4 = *(const float4*)&Xre[i*16 + bb];
        float4 m4 = *(const float4*)&Xim[i*16 + bb];
        cplx re01 = cpack(r4.x, r4.y), re23 = cpack(r4.z, r4.w);
        cplx im01 = cpack(m4.x, m4.y), im23 = cpack(m4.z, m4.w);
        ax01 = cfma2(re01, wx2,  ax01);  ax01 = cfma2(im01, wny2, ax01);
        ax23 = cfma2(re23, wx2,  ax23);  ax23 = cfma2(im23, wny2, ax23);
        ay01 = cfma2(re01, wy2,  ay01);  ay01 = cfma2(im01, wx2,  ay01);
        ay23 = cfma2(re23, wy2,  ay23);  ay23 = cfma2(im23, wx2,  ay23);
    }
    float2 a0 = make_float2(clo(ax01), clo(ay01));
    float2 a1 = make_float2(chi(ax01), chi(ay01));
    float2 a2 = make_float2(clo(ax23), clo(ay23));
    float2 a3 = make_float2(chi(ax23), chi(ay23));
    // stage Y into smem (reuse Ws), then emit (y0,y1) float4 per z, coalesced
    __syncthreads();                 // all GEMM reads of Ws done
    float2* Ysm = Ws;
    Ysm[(bb+0)*64 + o] = a0;
    Ysm[(bb+1)*64 + o] = a1;
    Ysm[(bb+2)*64 + o] = a2;
    Ysm[(bb+3)*64 + o] = a3;
    __syncthreads();
    for (int z = tid; z < 512; z += 256){
        float2 y0 = Ysm[2*z], y1 = Ysm[2*z + 1];
        g_Yp4[(size_t)jrow*512 + z] = make_float4(y0.x, y0.y, y1.x, y1.y);
    }
}

// ---------------- inverse -------------------------------------------------------
__global__ __launch_bounds__(384, 2) void inv_kernel(float* __restrict__ out,
                                                     const float* __restrict__ bias, int nPrim){
    extern __shared__ cplx smemBuf[];
    cplx* ctile = smemBuf;
    cplx* stg   = smemBuf + CTILE_CPLX;
    __shared__ float4 tw4[64];
    int tid = threadIdx.x, lane = tid & 31, wid = tid >> 5;
    if (tid < 64){ float2 e = g_E[tid]; tw4[tid] = make_float4(e.x, -e.y, e.y, e.x); }
    int b = blockIdx.x >> 5, op = blockIdx.x & 31;
    int o0 = 2*op;
    int bsrc = (b + 8) & 15;
    int osrc = (o0 + 32) & 63;
    {
        float4 z4 = make_float4(0.f, 0.f, 0.f, 0.f);
        float4* d4 = (float4*)ctile;
        for (int t = tid; t < CTILE_CPLX/2; t += 384) d4[t] = z4;
    }
    __syncthreads();

    // per-primary 16B scattered load -> two tile scatter writes (Zp, Zpr)
    float2* ct2 = (float2*)ctile;
    const float4* ycol = g_Yp4 + (bsrc*32 + (osrc >> 1));
    for (int j = tid; j < nPrim; j += 384){
        float4 y = __ldg(&ycol[(size_t)j*512]);
        int oa = g_pOffA[j], ob = g_pOffB[j];
        ct2[oa] = make_float2(y.x - y.w, y.y + y.z);
        ct2[ob] = make_float2(y.x + y.w, y.z - y.y);
    }
    __syncthreads();

    for (int t = tid; t < 512; t += 384){
        int c = t & 63, blk = t >> 6;
        dit16_body(ctile, tw4, c*TPC + blk*16, 1);
    }
    __syncthreads();
    for (int t = tid; t < 1024; t += 384){
        int j = t & 15, c = t >> 4;
        dit8_body(ctile, tw4, c*TPC + j, 16, j);
    }
    __syncthreads();

    float bv0 = bias[o0], bv1 = bias[o0 + 1];
    float* d0 = out + (size_t)(b*64 + o0) * 16384;
    float* d1 = d0 + 16384;
    const float sc = 1.f / 16384.f;
    cplx* wst = stg + wid*2*SPITCH;
    cplx zero = cpack(0.f, 0.f);
    for (int pr = wid; pr < 64; pr += 12){
        if (lane < 16){
            int rr = lane >> 3, blk = lane & 7;
            int row = 2*pr + rr;
            int rb = ((blk & 1) << 2) | (blk & 2) | (blk >> 2);
            cplx xv[16];
            #pragma unroll
            for (int m = 0; m < 16; m++){
                int v = V16[m] + rb;
                cplx val = zero;
                if (v <= 30)      val = ctile[v*TPC + row];
                else if (v >= 98) val = ctile[(v - 67)*TPC + row];
                xv[m] = val;
            }
            dit16_core(xv, tw4);
            cplx* dst = wst + rr*SPITCH + blk*17;
            #pragma unroll
            for (int m = 0; m < 16; m++) dst[m] = xv[m];
        }
        __syncwarp();
        {   int rr = lane >> 4, j = lane & 15;
            dit8_body(wst, tw4, rr*SPITCH + j, 17, j); }
        __syncwarp();
        #pragma unroll
        for (int rr = 0; rr < 2; rr++){
            int row = 2*pr + rr;
            const cplx* src = wst + rr*SPITCH + 4*lane + (lane >> 2);
            cplx w0 = src[0], w1 = src[1], w2 = src[2], w3 = src[3];
            ((float4*)(d0 + row*128))[lane] =
                make_float4(clo(w0)*sc + bv0, clo(w1)*sc + bv0, clo(w2)*sc + bv0, clo(w3)*sc + bv0);
            ((float4*)(d1 + row*128))[lane] =
                make_float4(chi(w0)*sc + bv1, chi(w1)*sc + bv1, chi(w2)*sc + bv1, chi(w3)*sc + bv1);
        }
        __syncwarp();
    }
}

// ---------------- launch --------------------------------------------------------
extern "C" void kernel_launch(void* const* d_in, const int* in_sizes, int n_in,
                              void* d_out, int out_size){
    const float* x    = (const float*)d_in[0];
    const float* wgt  = (const float*)d_in[1];
    const float* bias = (const float*)d_in[2];
    float* out = (float*)d_out;

    int nMask = 0;
    for (int u = 0; u < 128; u++){
        int du = (u < 64) ? u : u - 128;
        for (int v = 0; v < 128; v++){
            int dv = (v < 64) ? v : v - 128;
            if (du*du + dv*dv <= 900) nMask++;
        }
    }
    // primaries: u=0 with v<=30 (31 bins) + all masked bins with u in [1,30]
    int nPrim = 31;
    for (int u = 1; u <= 30; u++){
        int vm = 0;
        while ((vm + 1)*(vm + 1) <= 900 - u*u) vm++;
        nPrim += 2*vm + 1;
    }

    cudaFuncSetAttribute(fwd_kernel, cudaFuncAttributeMaxDynamicSharedMemorySize, (int)SMEM_BYTES);
    cudaFuncSetAttribute(inv_kernel, cudaFuncAttributeMaxDynamicSharedMemorySize, (int)SMEM_BYTES);

    setup_kernel<<<260, 1024>>>(wgt);
    fwd_kernel<<<512, 384, SMEM_BYTES>>>(x, nMask);
    mix_kernel<<<nMask, 256>>>(nMask);
    inv_kernel<<<512, 384, SMEM_BYTES>>>(out, bias, nPrim);
}

// round 17
// speedup vs baseline: 1.0929x; 1.0447x over previous
#include <cuda_runtime.h>

#define TPC 129                                     // compact tile pitch (h dim)
#define SPITCH 136                                  // padded staging row pitch (128 + 8)
#define NF_MAX 2850
#define CTILE_CPLX (64 * TPC)                       // 8256 cplx
#define STG_CPLX   (12 * 2 * SPITCH)                // 3264 cplx
#define SMEM_BYTES ((CTILE_CPLX + STG_CPLX) * 8)    // 92160 B

// ---------------- device scratch ------------------------------------------------
__device__ float2 g_E[128];
__device__ int    g_pUV[NF_MAX];                    // per-primary u*128+v
__device__ int    g_pOffA[NF_MAX];                  // per-primary tile offsets
__device__ int    g_pOffB[NF_MAX];                  // conj-partner tile offset
__device__ float2 g_A[61 * 3 * 4096];
__device__ float4 g_Xf4[(size_t)NF_MAX * 512];      // [j_primary][i*16+b] /2
__device__ float4 g_Yp4[(size_t)NF_MAX * 512];      // [j_primary][b*32+zo] = (y0, y1)
#define g_Xf ((float2*)g_Xf4)

typedef unsigned long long cplx;                    // packed (re, im) f32x2

__device__ __forceinline__ int brev7(int x) { return (int)(__brev((unsigned)x) >> 25); }

// ---------------- packed f32x2 complex helpers ----------------------------------
__device__ __forceinline__ cplx cpack(float x, float y){
    cplx r; asm("mov.b64 %0, {%1, %2};" : "=l"(r) : "f"(x), "f"(y)); return r;
}
__device__ __forceinline__ float clo(cplx a){
    float x; asm("{ .reg .f32 hi; mov.b64 {%0, hi}, %1; }" : "=f"(x) : "l"(a)); return x;
}
__device__ __forceinline__ float chi(cplx a){
    float y; asm("{ .reg .f32 lo; mov.b64 {lo, %0}, %1; }" : "=f"(y) : "l"(a)); return y;
}
__device__ __forceinline__ cplx cadd2(cplx a, cplx b){
    cplx r; asm("add.rn.f32x2 %0, %1, %2;" : "=l"(r) : "l"(a), "l"(b)); return r;
}
__device__ __forceinline__ cplx csub2(cplx a, cplx b){
    cplx r; asm("sub.rn.f32x2 %0, %1, %2;" : "=l"(r) : "l"(a), "l"(b)); return r;
}
__device__ __forceinline__ cplx cmul2(cplx a, cplx b){
    cplx r; asm("mul.rn.f32x2 %0, %1, %2;" : "=l"(r) : "l"(a), "l"(b)); return r;
}
__device__ __forceinline__ cplx cfma2(cplx a, cplx b, cplx c){
    cplx r; asm("fma.rn.f32x2 %0, %1, %2, %3;" : "=l"(r) : "l"(a), "l"(b), "l"(c)); return r;
}
__device__ __forceinline__ cplx cmulT(cplx b, float4 t){
    float bx = clo(b), by = chi(b);
    return cfma2(cpack(by, by), cpack(t.z, t.w), cmul2(cpack(bx, bx), cpack(t.x, t.y)));
}
__device__ __forceinline__ cplx cmulnegi(cplx a){
    float x = clo(a), y = chi(a); return cpack(y, -x);
}
__device__ __forceinline__ cplx cmulposi(cplx a){
    float x = clo(a), y = chi(a); return cpack(-y, x);
}

// ---------------- merged setup: prep_A (blocks 0..243) + init (blocks 244..259) --
__device__ __forceinline__ int vmaxOf(int rem){
    int vm = __float2int_rd(sqrtf((float)rem));
    while (vm*vm > rem) vm--;
    while ((vm+1)*(vm+1) <= rem) vm++;
    return vm;
}

__global__ __launch_bounds__(1024) void setup_kernel(const float* __restrict__ wgt){
    int blk = blockIdx.x, tid = threadIdx.x;
    if (blk < 244){
        __shared__ float2 se1, se2;
        int c = blk >> 2;
        if (tid == 0){
            int v = (c <= 30) ? c : c + 67;
            double a1 = -6.283185307179586476925286766559 * (double)v / 128.0;
            double a2 = -6.283185307179586476925286766559 * (double)((2*v) & 127) / 128.0;
            se1 = make_float2((float)cos(a1), (float)sin(a1));
            se2 = make_float2((float)cos(a2), (float)sin(a2));
        }
        __syncthreads();
        float2 e1 = se1, e2 = se2;
        int oi = ((blk & 3) << 10) + tid;
        const float* w9 = wgt + oi*9;
        #pragma unroll
        for (int p = 0; p < 3; p++){
            float w0 = w9[p*3], w1 = w9[p*3+1], w2 = w9[p*3+2];
            float2 acc;
            acc.x = w0 + w1*e1.x + w2*e2.x;
            acc.y =      w1*e1.y + w2*e2.y;
            g_A[((size_t)c*3 + p)*4096 + oi] = acc;
        }
    } else {
        __shared__ int vmax[128];
        __shared__ int primBase[32];
        int ib = blk - 244;
        if (ib == 0 && tid <= 32){
            double ang = -6.283185307179586476925286766559 * (double)tid / 128.0;
            float c = (float)cos(ang), s = (float)sin(ang);
            if (tid == 0)      { g_E[0]  = make_float2(1.f, 0.f);  g_E[64] = make_float2(-1.f, 0.f); }
            else if (tid == 32){ g_E[32] = make_float2(0.f, -1.f); g_E[96] = make_float2(0.f, 1.f); }
            else {
                g_E[tid]       = make_float2( c,  s);
                g_E[64 - tid]  = make_float2(-c,  s);
                g_E[64 + tid]  = make_float2(-c, -s);
                g_E[128 - tid] = make_float2( c, -s);
            }
        }
        if (tid < 128){
            int du = (tid < 64) ? tid : tid - 128;
            int rem = 900 - du*du;
            vmax[tid] = (rem >= 0) ? vmaxOf(rem) : -1;
        }
        __syncthreads();
        if (tid == 0){
            int pj = 31;                          // u=0 primaries: j = v for v in [0,30]
            for (int u = 1; u <= 30; u++){ primBase[u] = pj; pj += 2*vmax[u] + 1; }
            primBase[0] = 0;
        }
        __syncthreads();
        int t = ib * 1024 + tid;
        if (t < 16384){
            int u = t >> 7, v = t & 127;
            int vm = vmax[u];
            if (vm >= 0){
                int dv = (v < 64) ? v : v - 128;
                if (dv >= -vm && dv <= vm){
                    // primary iff u in [1,30], or u==0 && v<=30
                    bool isPrim = (u >= 1 && u <= 30) || (u == 0 && v <= 30);
                    if (isPrim){
                        int vr = (v <= vm) ? v : v - (128 - vm) + vm + 1;
                        int j = (u == 0) ? v : (primBase[u] + vr);
                        int uc = (128 - u) & 127, vc = (128 - v) & 127;
                        int cA = (v  <= 30) ? v  : v  - 67;
                        int cB = (vc <= 30) ? vc : vc - 67;
                        g_pUV[j]   = t;
                        g_pOffA[j] = cA*TPC + brev7(u);
                        g_pOffB[j] = cB*TPC + brev7(uc);
                    }
                }
            }
        }
    }
}

// ---------------- packed radix bodies -------------------------------------------
__device__ __forceinline__ void dif8_body(cplx* d, const float4* t4, int base, int stp, int j){
    cplx x[8];
    #pragma unroll
    for (int m = 0; m < 8; m++) x[m] = d[base + m*stp];
    #pragma unroll
    for (int m = 0; m < 4; m++){
        cplx a = x[m], b = x[m+4];
        x[m] = cadd2(a,b); x[m+4] = cmulT(csub2(a,b), t4[j + 16*m]);
    }
    {
        float4 w0 = t4[2*j], w1 = t4[2*j + 32]; cplx a, b;
        a=x[0]; b=x[2]; x[0]=cadd2(a,b); x[2]=cmulT(csub2(a,b), w0);
        a=x[1]; b=x[3]; x[1]=cadd2(a,b); x[3]=cmulT(csub2(a,b), w1);
        a=x[4]; b=x[6]; x[4]=cadd2(a,b); x[6]=cmulT(csub2(a,b), w0);
        a=x[5]; b=x[7]; x[5]=cadd2(a,b); x[7]=cmulT(csub2(a,b), w1);
    }
    {
        float4 w = t4[4*j];
        #pragma unroll
        for (int m = 0; m < 8; m += 2){
            cplx a = x[m], b = x[m+1];
            x[m] = cadd2(a,b); x[m+1] = cmulT(csub2(a,b), w);
        }
    }
    #pragma unroll
    for (int m = 0; m < 8; m++) d[base + m*stp] = x[m];
}

__device__ __forceinline__ void dif16_core(cplx* x, const float4* t4){
    #pragma unroll
    for (int m = 0; m < 8; m++){
        cplx a = x[m], b = x[m+8];
        x[m] = cadd2(a,b); x[m+8] = cmulT(csub2(a,b), t4[8*m]);
    }
    #pragma unroll
    for (int m = 0; m < 4; m++){
        float4 w = t4[16*m]; cplx a, b;
        a=x[m];   b=x[m+4];  x[m]  =cadd2(a,b); x[m+4] =cmulT(csub2(a,b), w);
        a=x[m+8]; b=x[m+12]; x[m+8]=cadd2(a,b); x[m+12]=cmulT(csub2(a,b), w);
    }
    #pragma unroll
    for (int g = 0; g < 4; g++){
        int b0 = 4*g; cplx a, b;
        a=x[b0];   b=x[b0+2]; x[b0]  =cadd2(a,b); x[b0+2]=csub2(a,b);
        a=x[b0+1]; b=x[b0+3]; x[b0+1]=cadd2(a,b); x[b0+3]=cmulnegi(csub2(a,b));
    }
    #pragma unroll
    for (int m = 0; m < 16; m += 2){
        cplx a = x[m], b = x[m+1];
        x[m] = cadd2(a,b); x[m+1] = csub2(a,b);
    }
}

__device__ __forceinline__ void dif16_body(cplx* d, const float4* t4, int base, int es){
    cplx x[16];
    #pragma unroll
    for (int m = 0; m < 16; m++) x[m] = d[base + m*es];
    dif16_core(x, t4);
    #pragma unroll
    for (int m = 0; m < 16; m++) d[base + m*es] = x[m];
}

__device__ __forceinline__ void dit16_core(cplx* x, const float4* t4){
    #pragma unroll
    for (int m = 0; m < 16; m += 2){
        cplx a = x[m], b = x[m+1];
        x[m] = cadd2(a,b); x[m+1] = csub2(a,b);
    }
    #pragma unroll
    for (int g = 0; g < 4; g++){
        int b0 = 4*g; cplx a, tt;
        a=x[b0];   tt=x[b0+2];           x[b0]  =cadd2(a,tt); x[b0+2]=csub2(a,tt);
        a=x[b0+1]; tt=cmulposi(x[b0+3]); x[b0+1]=cadd2(a,tt); x[b0+3]=csub2(a,tt);
    }
    #pragma unroll
    for (int m = 0; m < 4; m++){
        float4 w = t4[16*m]; cplx a, tt;
        a=x[m];   tt=cmulT(x[m+4],  w); x[m]  =cadd2(a,tt); x[m+4] =csub2(a,tt);
        a=x[m+8]; tt=cmulT(x[m+12], w); x[m+8]=cadd2(a,tt); x[m+12]=csub2(a,tt);
    }
    #pragma unroll
    for (int m = 0; m < 8; m++){
        cplx a = x[m], tt = cmulT(x[m+8], t4[8*m]);
        x[m] = cadd2(a,tt); x[m+8] = csub2(a,tt);
    }
}

__device__ __forceinline__ void dit16_body(cplx* d, const float4* t4, int base, int es){
    cplx x[16];
    #pragma unroll
    for (int m = 0; m < 16; m++) x[m] = d[base + m*es];
    dit16_core(x, t4);
    #pragma unroll
    for (int m = 0; m < 16; m++) d[base + m*es] = x[m];
}

__device__ __forceinline__ void dit8_body(cplx* d, const float4* t4, int base, int stp, int j){
    cplx x[8];
    #pragma unroll
    for (int m = 0; m < 8; m++) x[m] = d[base + m*stp];
    {
        float4 w = t4[4*j];
        #pragma unroll
        for (int m = 0; m < 8; m += 2){
            cplx a = x[m], tt = cmulT(x[m+1], w);
            x[m] = cadd2(a,tt); x[m+1] = csub2(a,tt);
        }
    }
    {
        float4 w0 = t4[2*j], w1 = t4[2*j + 32]; cplx a, tt;
        a=x[0]; tt=cmulT(x[2], w0); x[0]=cadd2(a,tt); x[2]=csub2(a,tt);
        a=x[1]; tt=cmulT(x[3], w1); x[1]=cadd2(a,tt); x[3]=csub2(a,tt);
        a=x[4]; tt=cmulT(x[6], w0); x[4]=cadd2(a,tt); x[6]=csub2(a,tt);
        a=x[5]; tt=cmulT(x[7], w1); x[5]=cadd2(a,tt); x[7]=csub2(a,tt);
    }
    #pragma unroll
    for (int m = 0; m < 4; m++){
        cplx a = x[m], tt = cmulT(x[m+4], t4[j + 16*m]);
        x[m] = cadd2(a,tt); x[m+4] = csub2(a,tt);
    }
    #pragma unroll
    for (int m = 0; m < 8; m++) d[base + m*stp] = x[m];
}

__device__ __constant__ int V16[16] = {0,64,32,96,16,80,48,112,8,72,40,104,24,88,56,120};

// ---------------- forward -------------------------------------------------------
__global__ __launch_bounds__(384, 2) void fwd_kernel(const float* __restrict__ x, int nPrim){
    extern __shared__ cplx smemBuf[];
    cplx* ctile = smemBuf;
    cplx* stg   = smemBuf + CTILE_CPLX;
    __shared__ float4 tw4[64];
    int tid = threadIdx.x, lane = tid & 31, wid = tid >> 5;
    if (tid < 64){ float2 e = g_E[tid]; tw4[tid] = make_float4(e.x, e.y, -e.y, e.x); }
    int b = blockIdx.x >> 5, ip = blockIdx.x & 31;
    int i0 = 2*ip;
    const float* s0 = x + (size_t)(b*64 + i0) * 16384;
    const float* s1 = s0 + 16384;
    __syncthreads();

    cplx* wst = stg + wid*2*SPITCH;
    for (int pr = wid; pr < 64; pr += 12){
        #pragma unroll
        for (int rr = 0; rr < 2; rr++){
            int row = 2*pr + rr;
            float4 a = ((const float4*)(s0 + row*128))[lane];
            float4 c = ((const float4*)(s1 + row*128))[lane];
            cplx* dst = wst + rr*SPITCH + 4*lane + (lane >> 2);
            dst[0] = cpack(a.x, c.x);
            dst[1] = cpack(a.y, c.y);
            dst[2] = cpack(a.z, c.z);
            dst[3] = cpack(a.w, c.w);
        }
        __syncwarp();
        {   int rr = lane >> 4, j = lane & 15;
            dif8_body(wst, tw4, rr*SPITCH + j, 17, j); }
        __syncwarp();
        if (lane < 16){
            int rr = lane >> 3, blk = lane & 7;
            int row = 2*pr + rr;
            int rb = ((blk & 1) << 2) | (blk & 2) | (blk >> 2);
            cplx xv[16];
            cplx* src = wst + rr*SPITCH + blk*17;
            #pragma unroll
            for (int m = 0; m < 16; m++) xv[m] = src[m];
            dif16_core(xv, tw4);
            #pragma unroll
            for (int m = 0; m < 16; m++){
                int v = V16[m] + rb;
                if (v <= 30)       ctile[v*TPC + row]        = xv[m];
                else if (v >= 98)  ctile[(v - 67)*TPC + row] = xv[m];
            }
        }
        __syncwarp();
    }
    __syncthreads();

    for (int t = tid; t < 1024; t += 384){
        int j = t & 15, c = t >> 4;
        dif8_body(ctile, tw4, c*TPC + j, 16, j);
    }
    __syncthreads();
    for (int t = tid; t < 512; t += 384){
        int c = t & 63, blk = t >> 6;
        dif16_body(ctile, tw4, c*TPC + blk*16, 1);
    }
    __syncthreads();

    // gather + Hermitian split over PRIMARIES only; g_Xf layout [j][i*16+b]
    float2* ct2 = (float2*)ctile;
    for (int j = tid; j < nPrim; j += 384){
        float2 z  = ct2[g_pOffA[j]];
        float2 zc = ct2[g_pOffB[j]];
        float2 X0 = make_float2(0.5f*(z.x + zc.x), 0.5f*(z.y - zc.y));
        float2 X1 = make_float2(0.5f*(z.y + zc.y), 0.5f*(zc.x - z.x));
        size_t base = (size_t)j*1024 + i0*16 + b;
        g_Xf[base]      = X0;
        g_Xf[base + 16] = X1;
    }
}

// ---------------- per-primary channel mix (grid = nPrim) ------------------------
__global__ __launch_bounds__(256) void mix_kernel(){
    __shared__ float Xre[1024];
    __shared__ float Xim[1024];
    __shared__ float2 Ws[64 * 65];   // [i][o]; reused as Ysm after GEMM
    int jp = blockIdx.x;
    int tid = threadIdx.x;
    int uv = g_pUV[jp];
    int u = uv >> 7, v = uv & 127;
    int c = (v <= 30) ? v : v - 67;
    float2 eu1 = g_E[u], eu2 = g_E[(2*u) & 127];
    for (int j = tid; j < 512; j += 256){
        float4 q = g_Xf4[(size_t)jp*512 + j];
        int b2 = j*2;
        Xre[b2]   = q.x;  Xim[b2]   = q.y;
        Xre[b2+1] = q.z;  Xim[b2+1] = q.w;
    }
    const float2* Ac = g_A + (size_t)c*3*4096;
    for (int oi = tid; oi < 4096; oi += 256){
        float2 a0 = Ac[oi], a1 = Ac[oi + 4096], a2 = Ac[oi + 8192];
        float2 wv;
        wv.x = a0.x + a1.x*eu1.x - a1.y*eu1.y + a2.x*eu2.x - a2.y*eu2.y;
        wv.y = a0.y + a1.x*eu1.y + a1.y*eu1.x + a2.x*eu2.y + a2.y*eu2.x;
        Ws[(oi & 63)*65 + (oi >> 6)] = wv;
    }
    __syncthreads();
    int o  = tid & 63;
    int bb = (tid >> 6) << 2;
    cplx ax01 = cpack(0.f,0.f), ax23 = ax01, ay01 = ax01, ay23 = ax01;
    #pragma unroll 8
    for (int i = 0; i < 64; i++){
        float2 w = Ws[i*65 + o];
        cplx wx2  = cpack(w.x,  w.x);
        cplx wy2  = cpack(w.y,  w.y);
        cplx wny2 = cpack(-w.y, -w.y);
        float4 r4 = *(const float4*)&Xre[i*16 + bb];
        float4 m4 = *(const float4*)&Xim[i*16 + bb];
        cplx re01 = cpack(r4.x, r4.y), re23 = cpack(r4.z, r4.w);
        cplx im01 = cpack(m4.x, m4.y), im23 = cpack(m4.z, m4.w);
        ax01 = cfma2(re01, wx2,  ax01);  ax01 = cfma2(im01, wny2, ax01);
        ax23 = cfma2(re23, wx2,  ax23);  ax23 = cfma2(im23, wny2, ax23);
        ay01 = cfma2(re01, wy2,  ay01);  ay01 = cfma2(im01, wx2,  ay01);
        ay23 = cfma2(re23, wy2,  ay23);  ay23 = cfma2(im23, wx2,  ay23);
    }
    float2 a0 = make_float2(clo(ax01), clo(ay01));
    float2 a1 = make_float2(chi(ax01), chi(ay01));
    float2 a2 = make_float2(clo(ax23), clo(ay23));
    float2 a3 = make_float2(chi(ax23), chi(ay23));
    // stage Y into smem (reuse Ws), then emit (y0,y1) float4 per z, coalesced
    __syncthreads();                 // all GEMM reads of Ws done
    float2* Ysm = Ws;
    Ysm[(bb+0)*64 + o] = a0;
    Ysm[(bb+1)*64 + o] = a1;
    Ysm[(bb+2)*64 + o] = a2;
    Ysm[(bb+3)*64 + o] = a3;
    __syncthreads();
    for (int z = tid; z < 512; z += 256){
        float2 y0 = Ysm[2*z], y1 = Ysm[2*z + 1];
        g_Yp4[(size_t)jp*512 + z] = make_float4(y0.x, y0.y, y1.x, y1.y);
    }
}

// ---------------- inverse -------------------------------------------------------
__global__ __launch_bounds__(384, 2) void inv_kernel(float* __restrict__ out,
                                                     const float* __restrict__ bias, int nPrim){
    extern __shared__ cplx smemBuf[];
    cplx* ctile = smemBuf;
    cplx* stg   = smemBuf + CTILE_CPLX;
    __shared__ float4 tw4[64];
    int tid = threadIdx.x, lane = tid & 31, wid = tid >> 5;
    if (tid < 64){ float2 e = g_E[tid]; tw4[tid] = make_float4(e.x, -e.y, e.y, e.x); }
    int b = blockIdx.x >> 5, op = blockIdx.x & 31;
    int o0 = 2*op;
    int bsrc = (b + 8) & 15;
    int osrc = (o0 + 32) & 63;
    {
        float4 z4 = make_float4(0.f, 0.f, 0.f, 0.f);
        float4* d4 = (float4*)ctile;
        for (int t = tid; t < CTILE_CPLX/2; t += 384) d4[t] = z4;
    }
    __syncthreads();

    // per-primary 16B scattered load -> two tile scatter writes (Zp, Zpr)
    float2* ct2 = (float2*)ctile;
    const float4* ycol = g_Yp4 + (bsrc*32 + (osrc >> 1));
    for (int j = tid; j < nPrim; j += 384){
        float4 y = __ldg(&ycol[(size_t)j*512]);
        int oa = g_pOffA[j], ob = g_pOffB[j];
        ct2[oa] = make_float2(y.x - y.w, y.y + y.z);
        ct2[ob] = make_float2(y.x + y.w, y.z - y.y);
    }
    __syncthreads();

    for (int t = tid; t < 512; t += 384){
        int c = t & 63, blk = t >> 6;
        dit16_body(ctile, tw4, c*TPC + blk*16, 1);
    }
    __syncthreads();
    for (int t = tid; t < 1024; t += 384){
        int j = t & 15, c = t >> 4;
        dit8_body(ctile, tw4, c*TPC + j, 16, j);
    }
    __syncthreads();

    float bv0 = bias[o0], bv1 = bias[o0 + 1];
    float* d0 = out + (size_t)(b*64 + o0) * 16384;
    float* d1 = d0 + 16384;
    const float sc = 1.f / 16384.f;
    cplx* wst = stg + wid*2*SPITCH;
    cplx zero = cpack(0.f, 0.f);
    for (int pr = wid; pr < 64; pr += 12){
        if (lane < 16){
            int rr = lane >> 3, blk = lane & 7;
            int row = 2*pr + rr;
            int rb = ((blk & 1) << 2) | (blk & 2) | (blk >> 2);
            cplx xv[16];
            #pragma unroll
            for (int m = 0; m < 16; m++){
                int v = V16[m] + rb;
                cplx val = zero;
                if (v <= 30)      val = ctile[v*TPC + row];
                else if (v >= 98) val = ctile[(v - 67)*TPC + row];
                xv[m] = val;
            }
            dit16_core(xv, tw4);
            cplx* dst = wst + rr*SPITCH + blk*17;
            #pragma unroll
            for (int m = 0; m < 16; m++) dst[m] = xv[m];
        }
        __syncwarp();
        {   int rr = lane >> 4, j = lane & 15;
            dit8_body(wst, tw4, rr*SPITCH + j, 17, j); }
        __syncwarp();
        #pragma unroll
        for (int rr = 0; rr < 2; rr++){
            int row = 2*pr + rr;
            const cplx* src = wst + rr*SPITCH + 4*lane + (lane >> 2);
            cplx w0 = src[0], w1 = src[1], w2 = src[2], w3 = src[3];
            ((float4*)(d0 + row*128))[lane] =
                make_float4(clo(w0)*sc + bv0, clo(w1)*sc + bv0, clo(w2)*sc + bv0, clo(w3)*sc + bv0);
            ((float4*)(d1 + row*128))[lane] =
                make_float4(chi(w0)*sc + bv1, chi(w1)*sc + bv1, chi(w2)*sc + bv1, chi(w3)*sc + bv1);
        }
        __syncwarp();
    }
}

// ---------------- launch --------------------------------------------------------
extern "C" void kernel_launch(void* const* d_in, const int* in_sizes, int n_in,
                              void* d_out, int out_size){
    const float* x    = (const float*)d_in[0];
    const float* wgt  = (const float*)d_in[1];
    const float* bias = (const float*)d_in[2];
    float* out = (float*)d_out;

    // primaries: u=0 with v<=30 (31 bins) + all masked bins with u in [1,30]
    int nPrim = 31;
    for (int u = 1; u <= 30; u++){
        int vm = 0;
        while ((vm + 1)*(vm + 1) <= 900 - u*u) vm++;
        nPrim += 2*vm + 1;
    }

    cudaFuncSetAttribute(fwd_kernel, cudaFuncAttributeMaxDynamicSharedMemorySize, (int)SMEM_BYTES);
    cudaFuncSetAttribute(inv_kernel, cudaFuncAttributeMaxDynamicSharedMemorySize, (int)SMEM_BYTES);

    setup_kernel<<<260, 1024>>>(wgt);
    fwd_kernel<<<512, 384, SMEM_BYTES>>>(x, nPrim);
    mix_kernel<<<nPrim, 256>>>();
    inv_kernel<<<512, 384, SMEM_BYTES>>>(out, bias, nPrim);
}